// round 1
// baseline (speedup 1.0000x reference)
#include <cuda_runtime.h>
#include <math.h>

#define Hh 128
#define EDd 16
#define EIN 272          // 2*H + ED
#define Nn 50000
#define Ee 500000
#define TILE_E 32
#define ETHREADS 256
#define LN_EPS 1e-5f

// ---- scratch (no runtime allocation allowed) ----
__device__ float g_hsrc[Nn * Hh];   // h @ src_W + src_b
__device__ float g_self[Nn * Hh];   // h @ self_W + self_b
__device__ float g_agg[Nn * Hh];    // scatter accumulator
__device__ float g_indeg[Nn];       // in-degree counts

__device__ __forceinline__ float gelu_exact(float x) {
    return 0.5f * x * (1.0f + erff(x * 0.70710678118654752440f));
}

// ---------------------------------------------------------------------------
// K0: zero agg + indeg
// ---------------------------------------------------------------------------
__global__ void zero_kernel() {
    long i = (long)blockIdx.x * blockDim.x + threadIdx.x;
    if (i < (long)Nn * Hh) {
        g_agg[i] = 0.0f;
    } else if (i < (long)Nn * Hh + Nn) {
        g_indeg[i - (long)Nn * Hh] = 0.0f;
    }
}

// ---------------------------------------------------------------------------
// K1: per-node projections  hsrc = h@src_W+b ; self = h@self_W+b
// 32 nodes / block, 256 threads, 4x4 register tiles, two weight mats per k.
// ---------------------------------------------------------------------------
__global__ void node_pre_kernel(const float* __restrict__ h,
                                const float* __restrict__ srcW,
                                const float* __restrict__ srcB,
                                const float* __restrict__ selfW,
                                const float* __restrict__ selfB) {
    __shared__ float sH[32 * Hh];
    const int tid = threadIdx.x;
    const int n0 = blockIdx.x * 32;

    const float4* h4 = (const float4*)h;
    for (int idx = tid; idx < 32 * 32; idx += ETHREADS) {
        int r = idx >> 5, c = idx & 31;
        int n = n0 + r;
        float4 v = (n < Nn) ? h4[(long)n * 32 + c] : make_float4(0.f, 0.f, 0.f, 0.f);
        *(float4*)&sH[r * Hh + c * 4] = v;
    }
    __syncthreads();

    const int e0 = (tid >> 5) << 2;   // node sub-tile 0..28
    const int j0 = (tid & 31) << 2;   // output col 0..124

    float a1[4][4] = {}, a2[4][4] = {};
#pragma unroll 4
    for (int k = 0; k < Hh; k++) {
        float4 w1 = __ldg((const float4*)(srcW + k * Hh + j0));
        float4 w2 = __ldg((const float4*)(selfW + k * Hh + j0));
#pragma unroll
        for (int i = 0; i < 4; i++) {
            float a = sH[(e0 + i) * Hh + k];
            a1[i][0] += a * w1.x; a1[i][1] += a * w1.y;
            a1[i][2] += a * w1.z; a1[i][3] += a * w1.w;
            a2[i][0] += a * w2.x; a2[i][1] += a * w2.y;
            a2[i][2] += a * w2.z; a2[i][3] += a * w2.w;
        }
    }
    float4 b1 = __ldg((const float4*)(srcB + j0));
    float4 b2 = __ldg((const float4*)(selfB + j0));
#pragma unroll
    for (int i = 0; i < 4; i++) {
        int n = n0 + e0 + i;
        if (n < Nn) {
            float4 o1 = make_float4(a1[i][0] + b1.x, a1[i][1] + b1.y,
                                    a1[i][2] + b1.z, a1[i][3] + b1.w);
            float4 o2 = make_float4(a2[i][0] + b2.x, a2[i][1] + b2.y,
                                    a2[i][2] + b2.z, a2[i][3] + b2.w);
            *(float4*)&g_hsrc[(long)n * Hh + j0] = o1;
            *(float4*)&g_self[(long)n * Hh + j0] = o2;
        }
    }
}

// ---------------------------------------------------------------------------
// K2: fused edge MLP + message + scatter
// 32 edges / block, 256 threads.
//   Ein = [h_src | h_dst | eattr]  (272)
//   hid = gelu(Ein @ W1 + b1)      (128)   -> reuses sBuf
//   ctx = hid @ W2 + b2            (256 = gate|shift)
//   msg = sigmoid(gate) * hsrc_proj[src] + shift  -> atomicAdd agg[dst]
// ---------------------------------------------------------------------------
__global__ void edge_kernel(const float* __restrict__ h,
                            const float* __restrict__ eattr,
                            const int* __restrict__ eidx,
                            const float* __restrict__ W1,
                            const float* __restrict__ b1,
                            const float* __restrict__ W2,
                            const float* __restrict__ b2) {
    __shared__ float sBuf[TILE_E * EIN];
    __shared__ int sSrc[TILE_E], sDst[TILE_E];

    const int tid = threadIdx.x;
    const int eb = blockIdx.x * TILE_E;

    if (tid < TILE_E) {
        sSrc[tid] = eidx[2 * (eb + tid)];
        sDst[tid] = eidx[2 * (eb + tid) + 1];
    }
    __syncthreads();

    // gather: 32 edges x 68 float4 (32 h_src + 32 h_dst + 4 eattr)
    const float4* h4 = (const float4*)h;
    const float4* ea4 = (const float4*)eattr;
    for (int idx = tid; idx < TILE_E * 68; idx += ETHREADS) {
        int e = idx / 68, c = idx - e * 68;
        float4 v;
        if (c < 32)      v = h4[(long)sSrc[e] * 32 + c];
        else if (c < 64) v = h4[(long)sDst[e] * 32 + (c - 32)];
        else             v = ea4[(long)(eb + e) * 4 + (c - 64)];
        *(float4*)&sBuf[e * EIN + c * 4] = v;
    }
    __syncthreads();

    const int e0 = (tid >> 5) << 2;   // edge sub-tile
    const int j0 = (tid & 31) << 2;   // col sub-tile

    // ---- GEMM1: (32 x 272) @ (272 x 128) ----
    float acc[4][4] = {};
#pragma unroll 2
    for (int k = 0; k < EIN; k++) {
        float4 w = __ldg((const float4*)(W1 + k * Hh + j0));
#pragma unroll
        for (int i = 0; i < 4; i++) {
            float a = sBuf[(e0 + i) * EIN + k];
            acc[i][0] += a * w.x; acc[i][1] += a * w.y;
            acc[i][2] += a * w.z; acc[i][3] += a * w.w;
        }
    }
    float4 bb = __ldg((const float4*)(b1 + j0));
    float hv[4][4];
#pragma unroll
    for (int i = 0; i < 4; i++) {
        hv[i][0] = gelu_exact(acc[i][0] + bb.x);
        hv[i][1] = gelu_exact(acc[i][1] + bb.y);
        hv[i][2] = gelu_exact(acc[i][2] + bb.z);
        hv[i][3] = gelu_exact(acc[i][3] + bb.w);
    }
    __syncthreads();   // all GEMM1 reads of sBuf done
#pragma unroll
    for (int i = 0; i < 4; i++) {
        *(float4*)&sBuf[(e0 + i) * EIN + j0] =
            make_float4(hv[i][0], hv[i][1], hv[i][2], hv[i][3]);
    }
    __syncthreads();

    // ---- GEMM2: (32 x 128) @ (128 x 256), gate & shift simultaneously ----
    float ag[4][4] = {}, as[4][4] = {};
#pragma unroll 2
    for (int k = 0; k < Hh; k++) {
        float4 wg = __ldg((const float4*)(W2 + k * 256 + j0));
        float4 ws = __ldg((const float4*)(W2 + k * 256 + 128 + j0));
#pragma unroll
        for (int i = 0; i < 4; i++) {
            float a = sBuf[(e0 + i) * EIN + k];
            ag[i][0] += a * wg.x; ag[i][1] += a * wg.y;
            ag[i][2] += a * wg.z; ag[i][3] += a * wg.w;
            as[i][0] += a * ws.x; as[i][1] += a * ws.y;
            as[i][2] += a * ws.z; as[i][3] += a * ws.w;
        }
    }
    float4 bg = __ldg((const float4*)(b2 + j0));
    float4 bs = __ldg((const float4*)(b2 + 128 + j0));
    float bgv[4] = {bg.x, bg.y, bg.z, bg.w};
    float bsv[4] = {bs.x, bs.y, bs.z, bs.w};

#pragma unroll
    for (int i = 0; i < 4; i++) {
        int e = e0 + i;
        int s = sSrc[e], d = sDst[e];
        const float* hp = g_hsrc + (long)s * Hh + j0;
        float* ap = g_agg + (long)d * Hh + j0;
#pragma unroll
        for (int jj = 0; jj < 4; jj++) {
            float gate = ag[i][jj] + bgv[jj];
            float shf  = as[i][jj] + bsv[jj];
            float sg = 1.0f / (1.0f + expf(-gate));
            float msg = sg * __ldg(hp + jj) + shf;
            atomicAdd(ap + jj, msg);
        }
    }
    if ((tid & 31) == 0) {
#pragma unroll
        for (int i = 0; i < 4; i++)
            atomicAdd(&g_indeg[sDst[e0 + i]], 1.0f);
    }
}

// ---------------------------------------------------------------------------
// K3: node update + residual GELU + LayerNorm
// 4 nodes / block, 128 threads.
// ---------------------------------------------------------------------------
__global__ void node_update_kernel(const float* __restrict__ h,
                                   const float* __restrict__ aggW,
                                   const float* __restrict__ aggB,
                                   const float* __restrict__ lng,
                                   const float* __restrict__ lnb,
                                   float* __restrict__ out) {
    __shared__ float sA[4][Hh];
    __shared__ float sX[4][Hh];

    const int tid = threadIdx.x;
    const int nb = blockIdx.x * 4;

#pragma unroll
    for (int i = 0; i < 4; i++) {
        int n = nb + i;
        if (n < Nn) {
            float rd = 1.0f / fmaxf(g_indeg[n], 1.0f);
            sA[i][tid] = g_agg[(long)n * Hh + tid] * rd;
        } else {
            sA[i][tid] = 0.0f;
        }
    }
    __syncthreads();

    float acc[4] = {};
#pragma unroll 4
    for (int k = 0; k < Hh; k++) {
        float w = __ldg(aggW + k * Hh + tid);
        acc[0] += sA[0][k] * w;
        acc[1] += sA[1][k] * w;
        acc[2] += sA[2][k] * w;
        acc[3] += sA[3][k] * w;
    }
    float ab = __ldg(aggB + tid);
#pragma unroll
    for (int i = 0; i < 4; i++) {
        int n = nb + i;
        if (n < Nn) {
            float u = g_self[(long)n * Hh + tid] + acc[i] + ab;
            sX[i][tid] = h[(long)n * Hh + tid] + gelu_exact(u);
        }
    }
    __syncthreads();

    // warp w normalizes node nb+w
    const int wid = tid >> 5, lane = tid & 31;
    const int n = nb + wid;
    if (n < Nn) {
        float v[4], s = 0.f, s2 = 0.f;
#pragma unroll
        for (int r = 0; r < 4; r++) {
            v[r] = sX[wid][lane + 32 * r];
            s += v[r];
            s2 += v[r] * v[r];
        }
#pragma unroll
        for (int o = 16; o > 0; o >>= 1) {
            s  += __shfl_xor_sync(0xffffffff, s, o);
            s2 += __shfl_xor_sync(0xffffffff, s2, o);
        }
        float mu = s * (1.0f / Hh);
        float var = s2 * (1.0f / Hh) - mu * mu;
        float rstd = rsqrtf(var + LN_EPS);
#pragma unroll
        for (int r = 0; r < 4; r++) {
            int j = lane + 32 * r;
            out[(long)n * Hh + j] =
                (v[r] - mu) * rstd * __ldg(lng + j) + __ldg(lnb + j);
        }
    }
}

// ---------------------------------------------------------------------------
extern "C" void kernel_launch(void* const* d_in, const int* in_sizes, int n_in,
                              void* d_out, int out_size) {
    const float* h     = (const float*)d_in[0];
    const float* eattr = (const float*)d_in[1];
    const int*   eidx  = (const int*)d_in[2];
    const float* srcW  = (const float*)d_in[3];
    const float* srcB  = (const float*)d_in[4];
    const float* e1W   = (const float*)d_in[5];
    const float* e1b   = (const float*)d_in[6];
    const float* e2W   = (const float*)d_in[7];
    const float* e2b   = (const float*)d_in[8];
    const float* selfW = (const float*)d_in[9];
    const float* selfB = (const float*)d_in[10];
    const float* aggW  = (const float*)d_in[11];
    const float* aggB  = (const float*)d_in[12];
    const float* lng   = (const float*)d_in[13];
    const float* lnb   = (const float*)d_in[14];
    float* out = (float*)d_out;

    int zero_blocks = ((long)Nn * Hh + Nn + 255) / 256;
    zero_kernel<<<zero_blocks, 256>>>();
    node_pre_kernel<<<(Nn + 31) / 32, ETHREADS>>>(h, srcW, srcB, selfW, selfB);
    edge_kernel<<<Ee / TILE_E, ETHREADS>>>(h, eattr, eidx, e1W, e1b, e2W, e2b);
    node_update_kernel<<<(Nn + 3) / 4, 128>>>(h, aggW, aggB, lng, lnb, out);
}

// round 3
// speedup vs baseline: 1.9757x; 1.9757x over previous
#include <cuda_runtime.h>
#include <cuda_bf16.h>
#include <math.h>
#include <cstdint>

#define Hh 128
#define Nn 50000
#define Ee 500000
#define LN_EPS 1e-5f
#define EB 128            // edges per CTA in edge kernel

// ---------------- scratch (module-level; no runtime alloc) ----------------
__device__ float g_P1[Nn * Hh];     // h @ e1_W[0:128]
__device__ float g_P2[Nn * Hh];     // h @ e1_W[128:256]
__device__ float g_S[Nn * Hh];      // h @ src_W + src_b
__device__ float g_self[Nn * Hh];   // h @ self_W + self_b
__device__ float g_agg[Nn * Hh];    // scatter accumulator
__device__ float g_indeg[Nn];
__device__ __align__(16) __nv_bfloat16 g_W2t[256 * 128];  // W2^T bf16, [n][k]

__device__ __forceinline__ float gelu_exact(float x) {
    return 0.5f * x * (1.0f + erff(x * 0.70710678118654752440f));
}

__device__ __forceinline__ uint32_t smem_u32(const void* p) {
    uint32_t a;
    asm("{ .reg .u64 t; cvta.to.shared.u64 t, %1; cvt.u32.u64 %0, t; }" : "=r"(a) : "l"(p));
    return a;
}

// ---------------------------------------------------------------------------
// K_w: W2^T -> bf16
// ---------------------------------------------------------------------------
__global__ void prep_w2_kernel(const float* __restrict__ W2) {
    int i = blockIdx.x * 256 + threadIdx.x;
    if (i < 256 * 128) {
        int n = i >> 7, k = i & 127;
        g_W2t[i] = __float2bfloat16(W2[k * 256 + n]);
    }
}

// ---------------------------------------------------------------------------
// K0: zero agg + indeg
// ---------------------------------------------------------------------------
__global__ void zero_kernel() {
    long i = (long)blockIdx.x * blockDim.x + threadIdx.x;
    if (i < (long)Nn * Hh) g_agg[i] = 0.0f;
    else if (i < (long)Nn * Hh + Nn) g_indeg[i - (long)Nn * Hh] = 0.0f;
}

// ---------------------------------------------------------------------------
// K1: per-node projections (4 GEMMs sharing the h tile)
// ---------------------------------------------------------------------------
__global__ void node_pre_kernel(const float* __restrict__ h,
                                const float* __restrict__ e1W,
                                const float* __restrict__ srcW,
                                const float* __restrict__ srcB,
                                const float* __restrict__ selfW,
                                const float* __restrict__ selfB) {
    __shared__ float sH[32 * Hh];
    const int tid = threadIdx.x;
    const int n0 = blockIdx.x * 32;
    const float* W1a = e1W;
    const float* W1b = e1W + 128 * Hh;

    const float4* h4 = (const float4*)h;
    for (int idx = tid; idx < 32 * 32; idx += 256) {
        int r = idx >> 5, c = idx & 31;
        int n = n0 + r;
        float4 v = (n < Nn) ? h4[(long)n * 32 + c] : make_float4(0.f, 0.f, 0.f, 0.f);
        *(float4*)&sH[r * Hh + c * 4] = v;
    }
    __syncthreads();

    const int e0 = (tid >> 5) << 2;
    const int j0 = (tid & 31) << 2;

    float a1[4][4] = {}, a2[4][4] = {}, a3[4][4] = {}, a4[4][4] = {};
#pragma unroll 2
    for (int k = 0; k < Hh; k++) {
        float4 w1 = __ldg((const float4*)(W1a + k * Hh + j0));
        float4 w2 = __ldg((const float4*)(W1b + k * Hh + j0));
        float4 w3 = __ldg((const float4*)(srcW + k * Hh + j0));
        float4 w4 = __ldg((const float4*)(selfW + k * Hh + j0));
#pragma unroll
        for (int i = 0; i < 4; i++) {
            float a = sH[(e0 + i) * Hh + k];
            a1[i][0] += a * w1.x; a1[i][1] += a * w1.y; a1[i][2] += a * w1.z; a1[i][3] += a * w1.w;
            a2[i][0] += a * w2.x; a2[i][1] += a * w2.y; a2[i][2] += a * w2.z; a2[i][3] += a * w2.w;
            a3[i][0] += a * w3.x; a3[i][1] += a * w3.y; a3[i][2] += a * w3.z; a3[i][3] += a * w3.w;
            a4[i][0] += a * w4.x; a4[i][1] += a * w4.y; a4[i][2] += a * w4.z; a4[i][3] += a * w4.w;
        }
    }
    float4 bs = __ldg((const float4*)(srcB + j0));
    float4 bf = __ldg((const float4*)(selfB + j0));
#pragma unroll
    for (int i = 0; i < 4; i++) {
        int n = n0 + e0 + i;
        if (n < Nn) {
            long o = (long)n * Hh + j0;
            *(float4*)&g_P1[o]   = make_float4(a1[i][0], a1[i][1], a1[i][2], a1[i][3]);
            *(float4*)&g_P2[o]   = make_float4(a2[i][0], a2[i][1], a2[i][2], a2[i][3]);
            *(float4*)&g_S[o]    = make_float4(a3[i][0] + bs.x, a3[i][1] + bs.y, a3[i][2] + bs.z, a3[i][3] + bs.w);
            *(float4*)&g_self[o] = make_float4(a4[i][0] + bf.x, a4[i][1] + bf.y, a4[i][2] + bf.z, a4[i][3] + bf.w);
        }
    }
}

// ---------------------------------------------------------------------------
// K2: edge kernel — per-thread hid (GELU) -> bf16 swizzled smem,
//     HMMA mma.sync 128x256x128, fused sigmoid-gate epilogue + red scatter.
// smem layout (bytes):
//   A    [128r x 128k bf16, 256B/row, chunk-XOR swz] @ 0      (32768)
//   B    [256n x 128k bf16, same layout]             @ 32768  (65536)
//   W1e  [16 x 128 f32]                              @ 98304  (8192)
//   b1   [128 f32]                                   @ 106496 (512)
//   b2   [256 f32]                                   @ 107008 (1024)
//   src  [128 i32]                                   @ 108032 (512)
//   dst  [128 i32]                                   @ 108544 (512)
// ---------------------------------------------------------------------------
#define SM_A    0
#define SM_B    32768
#define SM_W1E  98304
#define SM_B1   106496
#define SM_B2   107008
#define SM_SRC  108032
#define SM_DST  108544
#define SMEM_EDGE 109056

__device__ __forceinline__ void ldsm_x4(uint32_t* r, uint32_t addr) {
    asm volatile("ldmatrix.sync.aligned.m8n8.x4.shared.b16 {%0,%1,%2,%3}, [%4];"
                 : "=r"(r[0]), "=r"(r[1]), "=r"(r[2]), "=r"(r[3]) : "r"(addr));
}
__device__ __forceinline__ void ldsm_x2(uint32_t* r, uint32_t addr) {
    asm volatile("ldmatrix.sync.aligned.m8n8.x2.shared.b16 {%0,%1}, [%2];"
                 : "=r"(r[0]), "=r"(r[1]) : "r"(addr));
}
__device__ __forceinline__ void mma_bf16(float* c, const uint32_t* a, const uint32_t* b) {
    asm volatile(
        "mma.sync.aligned.m16n8k16.row.col.f32.bf16.bf16.f32 "
        "{%0,%1,%2,%3},{%4,%5,%6,%7},{%8,%9},{%0,%1,%2,%3};"
        : "+f"(c[0]), "+f"(c[1]), "+f"(c[2]), "+f"(c[3])
        : "r"(a[0]), "r"(a[1]), "r"(a[2]), "r"(a[3]), "r"(b[0]), "r"(b[1]));
}

__global__ void __launch_bounds__(128)
edge_kernel(const float* __restrict__ eattr,
            const int* __restrict__ eidx,
            const float* __restrict__ e1W,
            const float* __restrict__ e1b,
            const float* __restrict__ e2b) {
    extern __shared__ char smem[];
    const uint32_t sb = smem_u32(smem);
    const int tid = threadIdx.x;
    const int lane = tid & 31;
    const int wid = tid >> 5;
    float* w1e_s = (float*)(smem + SM_W1E);
    float* b1_s  = (float*)(smem + SM_B1);
    float* b2_s  = (float*)(smem + SM_B2);
    int* src_s   = (int*)(smem + SM_SRC);
    int* dst_s   = (int*)(smem + SM_DST);

    const long eb = (long)blockIdx.x * EB;
    const long e = eb + tid;
    const bool valid = (e < Ee);
    int s = 0, d = 0;
    if (valid) { s = eidx[2 * e]; d = eidx[2 * e + 1]; }
    src_s[tid] = s;
    dst_s[tid] = d;
    if (valid) atomicAdd(&g_indeg[d], 1.0f);
    const long ec = valid ? e : 0;

    // cooperative loads: W1e rows (256..271 of e1W), biases, B tile (swizzled)
    for (int i = tid; i < 16 * 128; i += 128) w1e_s[i] = e1W[256 * 128 + i];
    if (tid < 128) b1_s[tid] = e1b[tid];
    for (int i = tid; i < 256; i += 128) b2_s[i] = e2b[i];
#pragma unroll
    for (int it = 0; it < 32; it++) {
        int idx = tid + it * 128;           // 4096 chunks of 16B
        int n = idx >> 4, c = idx & 15;
        uint4 v = *(const uint4*)(g_W2t + n * 128 + c * 8);
        *(uint4*)(smem + SM_B + n * 256 + ((c ^ (n & 7)) << 4)) = v;
    }

    // eattr in registers
    float ea[16];
    {
        const float4* e4 = (const float4*)(eattr + ec * 16);
#pragma unroll
        for (int q = 0; q < 4; q++) {
            float4 v = e4[q];
            ea[4 * q] = v.x; ea[4 * q + 1] = v.y; ea[4 * q + 2] = v.z; ea[4 * q + 3] = v.w;
        }
    }

    // hid = gelu(P1[s] + P2[d] + b1 + eattr @ W1e), stored bf16 swizzled (row = tid)
    const float* p1 = g_P1 + (long)s * Hh;
    const float* p2 = g_P2 + (long)d * Hh;
#pragma unroll
    for (int jc = 0; jc < 4; jc++) {
        float pre[32];
#pragma unroll
        for (int q = 0; q < 8; q++) {
            float4 a = __ldg((const float4*)(p1 + jc * 32 + 4 * q));
            float4 b = __ldg((const float4*)(p2 + jc * 32 + 4 * q));
            float4 bb = *(const float4*)(b1_s + jc * 32 + 4 * q);
            pre[4 * q]     = a.x + b.x + bb.x;
            pre[4 * q + 1] = a.y + b.y + bb.y;
            pre[4 * q + 2] = a.z + b.z + bb.z;
            pre[4 * q + 3] = a.w + b.w + bb.w;
        }
#pragma unroll
        for (int k = 0; k < 16; k++) {
            float ev = ea[k];
            const float4* wr = (const float4*)(w1e_s + k * 128 + jc * 32);
#pragma unroll
            for (int q = 0; q < 8; q++) {
                float4 w = wr[q];
                pre[4 * q]     += ev * w.x;
                pre[4 * q + 1] += ev * w.y;
                pre[4 * q + 2] += ev * w.z;
                pre[4 * q + 3] += ev * w.w;
            }
        }
        uint32_t pk[16];
#pragma unroll
        for (int j = 0; j < 16; j++) {
            float x0 = gelu_exact(pre[2 * j]);
            float x1 = gelu_exact(pre[2 * j + 1]);
            __nv_bfloat162 t = __float22bfloat162_rn(make_float2(x0, x1));
            pk[j] = *reinterpret_cast<uint32_t*>(&t);
        }
#pragma unroll
        for (int part = 0; part < 4; part++) {
            int c = jc * 4 + part;
            uint4 v = make_uint4(pk[4 * part], pk[4 * part + 1], pk[4 * part + 2], pk[4 * part + 3]);
            *(uint4*)(smem + SM_A + tid * 256 + ((c ^ (tid & 7)) << 4)) = v;
        }
    }
    __syncthreads();

    // ---- HMMA: warp w does rows m0..m0+31, all N=256 ----
    const int m0 = wid * 32;

    // A fragments: Af[mt][kb][4]
    uint32_t Af[2][8][4];
    {
        int tsel = lane >> 3;
        int rowoff = ((tsel & 1) << 3) + (lane & 7);
        int chad = tsel >> 1;
#pragma unroll
        for (int mt = 0; mt < 2; mt++) {
            int row = m0 + mt * 16 + rowoff;
            uint32_t rb = sb + SM_A + row * 256;
            int rx = row & 7;
#pragma unroll
            for (int kb = 0; kb < 8; kb++) {
                int c = kb * 2 + chad;
                ldsm_x4(Af[mt][kb], rb + ((c ^ rx) << 4));
            }
        }
    }

    // grouped N loop: group g covers gate ntiles g*4..g*4+3 and shift +16
    const int tl = lane & 15;
    const int brow_off = tl & 7;
    const int bch_add = tl >> 3;

#pragma unroll 1
    for (int g = 0; g < 4; g++) {
        float Cg[2][4][4] = {}, Cs[2][4][4] = {};
#pragma unroll
        for (int kb = 0; kb < 8; kb++) {
            uint32_t Bg[4][2], Bs[4][2];
#pragma unroll
            for (int j = 0; j < 4; j++) {
                int ng = (g * 4 + j) * 8 + brow_off;          // gate row (n)
                int ns = 128 + (g * 4 + j) * 8 + brow_off;    // shift row
                int cg = (kb * 2 + bch_add);
                ldsm_x2(Bg[j], sb + SM_B + ng * 256 + ((cg ^ (ng & 7)) << 4));
                ldsm_x2(Bs[j], sb + SM_B + ns * 256 + ((cg ^ (ns & 7)) << 4));
            }
#pragma unroll
            for (int mt = 0; mt < 2; mt++)
#pragma unroll
                for (int j = 0; j < 4; j++) {
                    mma_bf16(Cg[mt][j], Af[mt][kb], Bg[j]);
                    mma_bf16(Cs[mt][j], Af[mt][kb], Bs[j]);
                }
        }
        // epilogue for this group
#pragma unroll
        for (int mt = 0; mt < 2; mt++) {
#pragma unroll
            for (int rh = 0; rh < 2; rh++) {
                int row = m0 + mt * 16 + (lane >> 2) + rh * 8;
                if (eb + row < Ee) {
                    int sr = src_s[row], dr = dst_s[row];
                    const float* Sp = g_S + (long)sr * Hh;
                    float* ap = g_agg + (long)dr * Hh;
#pragma unroll
                    for (int j = 0; j < 4; j++) {
                        int c0 = (g * 4 + j) * 8 + ((lane & 3) << 1);
                        float gt0 = Cg[mt][j][rh * 2]     + b2_s[c0];
                        float gt1 = Cg[mt][j][rh * 2 + 1] + b2_s[c0 + 1];
                        float sh0 = Cs[mt][j][rh * 2]     + b2_s[128 + c0];
                        float sh1 = Cs[mt][j][rh * 2 + 1] + b2_s[128 + c0 + 1];
                        float2 sv = *(const float2*)(Sp + c0);
                        float m0v = sv.x * __fdividef(1.0f, 1.0f + __expf(-gt0)) + sh0;
                        float m1v = sv.y * __fdividef(1.0f, 1.0f + __expf(-gt1)) + sh1;
                        asm volatile("red.global.add.v2.f32 [%0], {%1,%2};"
                                     :: "l"(ap + c0), "f"(m0v), "f"(m1v) : "memory");
                    }
                }
            }
        }
    }
}

// ---------------------------------------------------------------------------
// K3: node update + residual GELU + LayerNorm (4 nodes / block)
// ---------------------------------------------------------------------------
__global__ void node_update_kernel(const float* __restrict__ h,
                                   const float* __restrict__ aggW,
                                   const float* __restrict__ aggB,
                                   const float* __restrict__ lng,
                                   const float* __restrict__ lnb,
                                   float* __restrict__ out) {
    __shared__ float sA[4][Hh];
    __shared__ float sX[4][Hh];

    const int tid = threadIdx.x;
    const int nb = blockIdx.x * 4;

#pragma unroll
    for (int i = 0; i < 4; i++) {
        int n = nb + i;
        if (n < Nn) {
            float rd = 1.0f / fmaxf(g_indeg[n], 1.0f);
            sA[i][tid] = g_agg[(long)n * Hh + tid] * rd;
        } else sA[i][tid] = 0.0f;
    }
    __syncthreads();

    float acc[4] = {};
#pragma unroll 4
    for (int k = 0; k < Hh; k++) {
        float w = __ldg(aggW + k * Hh + tid);
        acc[0] += sA[0][k] * w;
        acc[1] += sA[1][k] * w;
        acc[2] += sA[2][k] * w;
        acc[3] += sA[3][k] * w;
    }
    float ab = __ldg(aggB + tid);
#pragma unroll
    for (int i = 0; i < 4; i++) {
        int n = nb + i;
        if (n < Nn) {
            float u = g_self[(long)n * Hh + tid] + acc[i] + ab;
            sX[i][tid] = h[(long)n * Hh + tid] + gelu_exact(u);
        }
    }
    __syncthreads();

    const int wid = tid >> 5, lane = tid & 31;
    const int n = nb + wid;
    if (n < Nn) {
        float v[4], sm = 0.f, s2 = 0.f;
#pragma unroll
        for (int r = 0; r < 4; r++) {
            v[r] = sX[wid][lane + 32 * r];
            sm += v[r];
            s2 += v[r] * v[r];
        }
#pragma unroll
        for (int o = 16; o > 0; o >>= 1) {
            sm += __shfl_xor_sync(0xffffffff, sm, o);
            s2 += __shfl_xor_sync(0xffffffff, s2, o);
        }
        float mu = sm * (1.0f / Hh);
        float var = s2 * (1.0f / Hh) - mu * mu;
        float rstd = rsqrtf(var + LN_EPS);
#pragma unroll
        for (int r = 0; r < 4; r++) {
            int j = lane + 32 * r;
            out[(long)n * Hh + j] = (v[r] - mu) * rstd * __ldg(lng + j) + __ldg(lnb + j);
        }
    }
}

// ---------------------------------------------------------------------------
extern "C" void kernel_launch(void* const* d_in, const int* in_sizes, int n_in,
                              void* d_out, int out_size) {
    const float* h     = (const float*)d_in[0];
    const float* eattr = (const float*)d_in[1];
    const int*   eidx  = (const int*)d_in[2];
    const float* srcW  = (const float*)d_in[3];
    const float* srcB  = (const float*)d_in[4];
    const float* e1W   = (const float*)d_in[5];
    const float* e1b   = (const float*)d_in[6];
    const float* e2W   = (const float*)d_in[7];
    const float* e2b   = (const float*)d_in[8];
    const float* selfW = (const float*)d_in[9];
    const float* selfB = (const float*)d_in[10];
    const float* aggW  = (const float*)d_in[11];
    const float* aggB  = (const float*)d_in[12];
    const float* lng   = (const float*)d_in[13];
    const float* lnb   = (const float*)d_in[14];
    float* out = (float*)d_out;

    cudaFuncSetAttribute(edge_kernel, cudaFuncAttributeMaxDynamicSharedMemorySize, SMEM_EDGE);

    int zero_blocks = (int)(((long)Nn * Hh + Nn + 255) / 256);
    zero_kernel<<<zero_blocks, 256>>>();
    prep_w2_kernel<<<(256 * 128 + 255) / 256, 256>>>(e2W);
    node_pre_kernel<<<(Nn + 31) / 32, 256>>>(h, e1W, srcW, srcB, selfW, selfB);
    edge_kernel<<<(Ee + EB - 1) / EB, 128, SMEM_EDGE>>>(eattr, eidx, e1W, e1b, e2b);
    node_update_kernel<<<(Nn + 3) / 4, 128>>>(h, aggW, aggB, lng, lnb, out);
}

// round 4
// speedup vs baseline: 2.9729x; 1.5047x over previous
#include <cuda_runtime.h>
#include <cuda_bf16.h>
#include <math.h>
#include <cstdint>

#define Hh 128
#define Nn 50000
#define Ee 500000
#define LN_EPS 1e-5f
#define EB 128
#define NT ((Ee + EB - 1) / EB)     // 3907 tiles
#define EGRID 296                    // persistent CTAs (2/SM)

// ---------------- scratch ----------------
__device__ float g_P1[Nn * Hh];
__device__ float g_P2[Nn * Hh];
__device__ float g_S[Nn * Hh];
__device__ float g_self[Nn * Hh];
__device__ float g_agg[Nn * Hh];
__device__ float g_indeg[Nn];
__device__ __align__(16) __nv_bfloat16 g_W2t[256 * 128];   // W2^T bf16 [n][k]

__device__ __forceinline__ float gelu_exact(float x) {
    return 0.5f * x * (1.0f + erff(x * 0.70710678118654752440f));
}
__device__ __forceinline__ uint32_t smem_u32(const void* p) {
    uint32_t a;
    asm("{ .reg .u64 t; cvta.to.shared.u64 t, %1; cvt.u32.u64 %0, t; }" : "=r"(a) : "l"(p));
    return a;
}
__device__ __forceinline__ void ldsm_x4(uint32_t* r, uint32_t addr) {
    asm volatile("ldmatrix.sync.aligned.m8n8.x4.shared.b16 {%0,%1,%2,%3}, [%4];"
                 : "=r"(r[0]), "=r"(r[1]), "=r"(r[2]), "=r"(r[3]) : "r"(addr));
}
__device__ __forceinline__ void ldsm_x2(uint32_t* r, uint32_t addr) {
    asm volatile("ldmatrix.sync.aligned.m8n8.x2.shared.b16 {%0,%1}, [%2];"
                 : "=r"(r[0]), "=r"(r[1]) : "r"(addr));
}
__device__ __forceinline__ void mma_bf16(float* c, const uint32_t* a, const uint32_t* b) {
    asm volatile(
        "mma.sync.aligned.m16n8k16.row.col.f32.bf16.bf16.f32 "
        "{%0,%1,%2,%3},{%4,%5,%6,%7},{%8,%9},{%0,%1,%2,%3};"
        : "+f"(c[0]), "+f"(c[1]), "+f"(c[2]), "+f"(c[3])
        : "r"(a[0]), "r"(a[1]), "r"(a[2]), "r"(a[3]), "r"(b[0]), "r"(b[1]));
}
__device__ __forceinline__ uint32_t pack_bf16(float a, float b) {
    __nv_bfloat162 t = __float22bfloat162_rn(make_float2(a, b));
    return *reinterpret_cast<uint32_t*>(&t);
}

// ---------------------------------------------------------------------------
__global__ void prep_w2_kernel(const float* __restrict__ W2) {
    int i = blockIdx.x * 256 + threadIdx.x;
    if (i < 256 * 128) {
        int n = i >> 7, k = i & 127;
        g_W2t[i] = __float2bfloat16(W2[k * 256 + n]);
    }
}
__global__ void zero_kernel() {
    long i = (long)blockIdx.x * blockDim.x + threadIdx.x;
    if (i < (long)Nn * Hh) g_agg[i] = 0.0f;
    else if (i < (long)Nn * Hh + Nn) g_indeg[i - (long)Nn * Hh] = 0.0f;
}

// ---------------------------------------------------------------------------
// K1: per-node projections (unchanged, FFMA)
// ---------------------------------------------------------------------------
__global__ void node_pre_kernel(const float* __restrict__ h,
                                const float* __restrict__ e1W,
                                const float* __restrict__ srcW,
                                const float* __restrict__ srcB,
                                const float* __restrict__ selfW,
                                const float* __restrict__ selfB) {
    __shared__ float sH[32 * Hh];
    const int tid = threadIdx.x;
    const int n0 = blockIdx.x * 32;
    const float* W1a = e1W;
    const float* W1b = e1W + 128 * Hh;

    const float4* h4 = (const float4*)h;
    for (int idx = tid; idx < 32 * 32; idx += 256) {
        int r = idx >> 5, c = idx & 31;
        int n = n0 + r;
        float4 v = (n < Nn) ? h4[(long)n * 32 + c] : make_float4(0.f, 0.f, 0.f, 0.f);
        *(float4*)&sH[r * Hh + c * 4] = v;
    }
    __syncthreads();

    const int e0 = (tid >> 5) << 2;
    const int j0 = (tid & 31) << 2;

    float a1[4][4] = {}, a2[4][4] = {}, a3[4][4] = {}, a4[4][4] = {};
#pragma unroll 2
    for (int k = 0; k < Hh; k++) {
        float4 w1 = __ldg((const float4*)(W1a + k * Hh + j0));
        float4 w2 = __ldg((const float4*)(W1b + k * Hh + j0));
        float4 w3 = __ldg((const float4*)(srcW + k * Hh + j0));
        float4 w4 = __ldg((const float4*)(selfW + k * Hh + j0));
#pragma unroll
        for (int i = 0; i < 4; i++) {
            float a = sH[(e0 + i) * Hh + k];
            a1[i][0] += a * w1.x; a1[i][1] += a * w1.y; a1[i][2] += a * w1.z; a1[i][3] += a * w1.w;
            a2[i][0] += a * w2.x; a2[i][1] += a * w2.y; a2[i][2] += a * w2.z; a2[i][3] += a * w2.w;
            a3[i][0] += a * w3.x; a3[i][1] += a * w3.y; a3[i][2] += a * w3.z; a3[i][3] += a * w3.w;
            a4[i][0] += a * w4.x; a4[i][1] += a * w4.y; a4[i][2] += a * w4.z; a4[i][3] += a * w4.w;
        }
    }
    float4 bs = __ldg((const float4*)(srcB + j0));
    float4 bf = __ldg((const float4*)(selfB + j0));
#pragma unroll
    for (int i = 0; i < 4; i++) {
        int n = n0 + e0 + i;
        if (n < Nn) {
            long o = (long)n * Hh + j0;
            *(float4*)&g_P1[o]   = make_float4(a1[i][0], a1[i][1], a1[i][2], a1[i][3]);
            *(float4*)&g_P2[o]   = make_float4(a2[i][0], a2[i][1], a2[i][2], a2[i][3]);
            *(float4*)&g_S[o]    = make_float4(a3[i][0] + bs.x, a3[i][1] + bs.y, a3[i][2] + bs.z, a3[i][3] + bs.w);
            *(float4*)&g_self[o] = make_float4(a4[i][0] + bf.x, a4[i][1] + bf.y, a4[i][2] + bf.z, a4[i][3] + bf.w);
        }
    }
}

// ---------------------------------------------------------------------------
// K2: persistent edge kernel, back-to-back MMA, no A smem tile.
// smem layout:
//   B2    [256n x 128k bf16, 256B/row XOR-swz]  @ 0       (65536)
//   W1T   [128n x 16k bf16, 32B/row]            @ 65536   (4096)
//   EST   [128e x 16 bf16, 32B/row]             @ 69632   (4096)
//   b1    [128 f32]                             @ 73728   (512)
//   b2    [256 f32]                             @ 74240   (1024)
//   src   [128 i32]                             @ 75264   (512)
//   dst   [128 i32]                             @ 75776   (512)
#define SM_B2   0
#define SM_W1T  65536
#define SM_EST  69632
#define SM_B1   73728
#define SM_B2B  74240
#define SM_SRC  75264
#define SM_DST  75776
#define SMEM_EDGE 76288

__global__ void __launch_bounds__(256, 2)
edge_kernel(const float* __restrict__ eattr,
            const int* __restrict__ eidx,
            const float* __restrict__ e1W,
            const float* __restrict__ e1b,
            const float* __restrict__ e2b) {
    extern __shared__ char smem[];
    const uint32_t sb = smem_u32(smem);
    const int tid = threadIdx.x;
    const int lane = tid & 31;
    const int wid = tid >> 5;           // 0..7, warp owns rows wid*16..+15
    float* b1_s = (float*)(smem + SM_B1);
    float* b2_s = (float*)(smem + SM_B2B);
    int* src_s  = (int*)(smem + SM_SRC);
    int* dst_s  = (int*)(smem + SM_DST);

    // ---- one-time staging ----
#pragma unroll
    for (int it = 0; it < 16; it++) {               // B2 swizzled
        int idx = tid + it * 256;
        int n = idx >> 4, c = idx & 15;
        uint4 v = *(const uint4*)(g_W2t + n * 128 + c * 8);
        *(uint4*)(smem + SM_B2 + n * 256 + ((c ^ (n & 7)) << 4)) = v;
    }
    for (int i = tid; i < 128 * 16; i += 256) {     // W1e^T bf16 [n][k]
        int n = i >> 4, k = i & 15;
        ((__nv_bfloat16*)(smem + SM_W1T))[n * 16 + k] =
            __float2bfloat16(e1W[(256 + k) * 128 + n]);
    }
    if (tid < 128) b1_s[tid] = e1b[tid];
    b2_s[tid & 255] = e2b[tid & 255];

    const int m0 = wid * 16;
    const int r0 = lane >> 2;
    const int rowA = m0 + r0, rowB = rowA + 8;
    const int cbase = (lane & 3) * 2;
    const int tl8 = lane & 15;

    for (int tile = blockIdx.x; tile < NT; tile += EGRID) {
        const long eb = (long)tile * EB;
        __syncthreads();     // prior tile fully consumed

        if (tid < 128) {
            long e = eb + tid;
            int s = 0, d = 0;
            if (e < Ee) {
                s = eidx[2 * e];
                d = eidx[2 * e + 1];
                atomicAdd(&g_indeg[d], 1.0f);
            }
            src_s[tid] = s;
            dst_s[tid] = d;
        }
        {   // stage eattr bf16: thread -> (edge tid>>1, half tid&1)
            long e = eb + (tid >> 1);
            long ec = (e < Ee) ? e : 0;
            const float4* p = (const float4*)(eattr + ec * 16 + (tid & 1) * 8);
            float4 v0 = p[0], v1 = p[1];
            uint4 w;
            w.x = pack_bf16(v0.x, v0.y); w.y = pack_bf16(v0.z, v0.w);
            w.z = pack_bf16(v1.x, v1.y); w.w = pack_bf16(v1.z, v1.w);
            *(uint4*)(smem + SM_EST + (tid >> 1) * 32 + (tid & 1) * 16) = w;
        }
        __syncthreads();

        const int sa = src_s[rowA], da = dst_s[rowA];
        const int sb2 = src_s[rowB], db = dst_s[rowB];
        const float* p1a = g_P1 + (long)sa * Hh;
        const float* p2a = g_P2 + (long)da * Hh;
        const float* p1b = g_P1 + (long)sb2 * Hh;
        const float* p2b = g_P2 + (long)db * Hh;

        // ---- C1 init = P1[s] + P2[d] + b1, in mma-C fragment layout ----
        float C1[16][4];
#pragma unroll
        for (int j = 0; j < 16; j++) {
            int c = j * 8 + cbase;
            float2 x1 = *(const float2*)(p1a + c);
            float2 x2 = *(const float2*)(p2a + c);
            float2 y1 = *(const float2*)(p1b + c);
            float2 y2 = *(const float2*)(p2b + c);
            float2 bb = *(const float2*)(b1_s + c);
            C1[j][0] = x1.x + x2.x + bb.x;
            C1[j][1] = x1.y + x2.y + bb.y;
            C1[j][2] = y1.x + y2.x + bb.x;
            C1[j][3] = y1.y + y2.y + bb.y;
        }

        // ---- MMA1: C1 += eattr(16) @ W1e(16x128) ----
        uint32_t A1[4];
        {
            int tsel = lane >> 3;
            int row = m0 + ((tsel & 1) << 3) + (lane & 7);
            ldsm_x4(A1, sb + SM_EST + row * 32 + ((tsel >> 1) << 4));
        }
#pragma unroll
        for (int j = 0; j < 16; j++) {
            uint32_t Bf[2];
            int n = j * 8 + (tl8 & 7);
            ldsm_x2(Bf, sb + SM_W1T + n * 32 + ((tl8 >> 3) << 4));
            mma_bf16(C1[j], A1, Bf);
        }

        // ---- GELU + repack C1 -> A2 fragments ----
        uint32_t A2[8][4];
#pragma unroll
        for (int kb = 0; kb < 8; kb++) {
            A2[kb][0] = pack_bf16(gelu_exact(C1[2 * kb][0]),     gelu_exact(C1[2 * kb][1]));
            A2[kb][1] = pack_bf16(gelu_exact(C1[2 * kb][2]),     gelu_exact(C1[2 * kb][3]));
            A2[kb][2] = pack_bf16(gelu_exact(C1[2 * kb + 1][0]), gelu_exact(C1[2 * kb + 1][1]));
            A2[kb][3] = pack_bf16(gelu_exact(C1[2 * kb + 1][2]), gelu_exact(C1[2 * kb + 1][3]));
        }

        // ---- MMA2 + fused epilogue, 8 groups of 16 cols ----
        const bool va = (eb + rowA < Ee), vb = (eb + rowB < Ee);
        const float* Spa = g_S + (long)sa * Hh;
        const float* Spb = g_S + (long)sb2 * Hh;
        float* apa = g_agg + (long)da * Hh;
        float* apb = g_agg + (long)db * Hh;

#pragma unroll 1
        for (int g = 0; g < 8; g++) {
            float Cg[2][4] = {}, Cs[2][4] = {};
#pragma unroll
            for (int kb = 0; kb < 8; kb++) {
                uint32_t Bg[2][2], Bs[2][2];
#pragma unroll
                for (int jj = 0; jj < 2; jj++) {
                    int ng = (2 * g + jj) * 8 + (tl8 & 7);
                    int ns = ng + 128;
                    int cg = kb * 2 + (tl8 >> 3);
                    ldsm_x2(Bg[jj], sb + SM_B2 + ng * 256 + ((cg ^ (ng & 7)) << 4));
                    ldsm_x2(Bs[jj], sb + SM_B2 + ns * 256 + ((cg ^ (ns & 7)) << 4));
                }
#pragma unroll
                for (int jj = 0; jj < 2; jj++) {
                    mma_bf16(Cg[jj], A2[kb], Bg[jj]);
                    mma_bf16(Cs[jj], A2[kb], Bs[jj]);
                }
            }
#pragma unroll
            for (int jj = 0; jj < 2; jj++) {
                int c0 = (2 * g + jj) * 8 + cbase;
                float2 bg = *(const float2*)(b2_s + c0);
                float2 bsv = *(const float2*)(b2_s + 128 + c0);
                if (va) {
                    float2 sv = *(const float2*)(Spa + c0);
                    float g0 = Cg[jj][0] + bg.x, g1 = Cg[jj][1] + bg.y;
                    float s0 = Cs[jj][0] + bsv.x, s1 = Cs[jj][1] + bsv.y;
                    float v0 = sv.x * __fdividef(1.0f, 1.0f + __expf(-g0)) + s0;
                    float v1 = sv.y * __fdividef(1.0f, 1.0f + __expf(-g1)) + s1;
                    asm volatile("red.global.add.v2.f32 [%0], {%1,%2};"
                                 :: "l"(apa + c0), "f"(v0), "f"(v1) : "memory");
                }
                if (vb) {
                    float2 sv = *(const float2*)(Spb + c0);
                    float g0 = Cg[jj][2] + bg.x, g1 = Cg[jj][3] + bg.y;
                    float s0 = Cs[jj][2] + bsv.x, s1 = Cs[jj][3] + bsv.y;
                    float v0 = sv.x * __fdividef(1.0f, 1.0f + __expf(-g0)) + s0;
                    float v1 = sv.y * __fdividef(1.0f, 1.0f + __expf(-g1)) + s1;
                    asm volatile("red.global.add.v2.f32 [%0], {%1,%2};"
                                 :: "l"(apb + c0), "f"(v0), "f"(v1) : "memory");
                }
            }
        }
    }
}

// ---------------------------------------------------------------------------
// K3: node update + residual GELU + LayerNorm (8 nodes / block)
// ---------------------------------------------------------------------------
__global__ void node_update_kernel(const float* __restrict__ h,
                                   const float* __restrict__ aggW,
                                   const float* __restrict__ aggB,
                                   const float* __restrict__ lng,
                                   const float* __restrict__ lnb,
                                   float* __restrict__ out) {
    __shared__ float sA[8][Hh];
    __shared__ float sX[8][Hh];

    const int tid = threadIdx.x;
    const int nb = blockIdx.x * 8;

#pragma unroll
    for (int i = 0; i < 8; i++) {
        int n = nb + i;
        if (n < Nn) {
            float rd = 1.0f / fmaxf(g_indeg[n], 1.0f);
            sA[i][tid] = g_agg[(long)n * Hh + tid] * rd;
        } else sA[i][tid] = 0.0f;
    }
    __syncthreads();

    float acc[8] = {};
#pragma unroll 4
    for (int k = 0; k < Hh; k++) {
        float w = __ldg(aggW + k * Hh + tid);
#pragma unroll
        for (int i = 0; i < 8; i++) acc[i] += sA[i][k] * w;
    }
    float ab = __ldg(aggB + tid);
#pragma unroll
    for (int i = 0; i < 8; i++) {
        int n = nb + i;
        if (n < Nn) {
            float u = g_self[(long)n * Hh + tid] + acc[i] + ab;
            sX[i][tid] = h[(long)n * Hh + tid] + gelu_exact(u);
        }
    }
    __syncthreads();

    const int wid = tid >> 5, lane = tid & 31;
#pragma unroll
    for (int pass = 0; pass < 2; pass++) {
        int ni = wid + pass * 4;
        int n = nb + ni;
        if (n < Nn) {
            float v[4], sm = 0.f, s2 = 0.f;
#pragma unroll
            for (int r = 0; r < 4; r++) {
                v[r] = sX[ni][lane + 32 * r];
                sm += v[r];
                s2 += v[r] * v[r];
            }
#pragma unroll
            for (int o = 16; o > 0; o >>= 1) {
                sm += __shfl_xor_sync(0xffffffff, sm, o);
                s2 += __shfl_xor_sync(0xffffffff, s2, o);
            }
            float mu = sm * (1.0f / Hh);
            float var = s2 * (1.0f / Hh) - mu * mu;
            float rstd = rsqrtf(var + LN_EPS);
#pragma unroll
            for (int r = 0; r < 4; r++) {
                int j = lane + 32 * r;
                out[(long)n * Hh + j] = (v[r] - mu) * rstd * __ldg(lng + j) + __ldg(lnb + j);
            }
        }
    }
}

// ---------------------------------------------------------------------------
extern "C" void kernel_launch(void* const* d_in, const int* in_sizes, int n_in,
                              void* d_out, int out_size) {
    const float* h     = (const float*)d_in[0];
    const float* eattr = (const float*)d_in[1];
    const int*   eidx  = (const int*)d_in[2];
    const float* srcW  = (const float*)d_in[3];
    const float* srcB  = (const float*)d_in[4];
    const float* e1W   = (const float*)d_in[5];
    const float* e1b   = (const float*)d_in[6];
    const float* e2W   = (const float*)d_in[7];
    const float* e2b   = (const float*)d_in[8];
    const float* selfW = (const float*)d_in[9];
    const float* selfB = (const float*)d_in[10];
    const float* aggW  = (const float*)d_in[11];
    const float* aggB  = (const float*)d_in[12];
    const float* lng   = (const float*)d_in[13];
    const float* lnb   = (const float*)d_in[14];
    float* out = (float*)d_out;

    cudaFuncSetAttribute(edge_kernel, cudaFuncAttributeMaxDynamicSharedMemorySize, SMEM_EDGE);

    int zero_blocks = (int)(((long)Nn * Hh + Nn + 255) / 256);
    zero_kernel<<<zero_blocks, 256>>>();
    prep_w2_kernel<<<(256 * 128 + 255) / 256, 256>>>(e2W);
    node_pre_kernel<<<(Nn + 31) / 32, 256>>>(h, e1W, srcW, srcB, selfW, selfB);
    edge_kernel<<<EGRID, 256, SMEM_EDGE>>>(eattr, eidx, e1W, e1b, e2b);
    node_update_kernel<<<(Nn + 7) / 8, 128>>>(h, aggW, aggB, lng, lnb, out);
}

// round 6
// speedup vs baseline: 3.8009x; 1.2785x over previous
#include <cuda_runtime.h>
#include <cuda_bf16.h>
#include <math.h>
#include <cstdint>

#define Hh 128
#define Nn 50000
#define Ee 500000
#define LN_EPS 1e-5f
#define EB 256
#define NT ((Ee + EB - 1) / EB)     // 1954 tiles
#define EGRID 296

// ---------------- scratch ----------------
__device__ float g_P1[Nn * Hh];
__device__ float g_P2[Nn * Hh];
__device__ float g_S[Nn * Hh];
__device__ float g_self[Nn * Hh];
__device__ float g_agg[Nn * Hh];
__device__ float g_indeg[Nn];
__device__ __align__(16) __nv_bfloat16 g_W2t[256 * 128];   // W2^T bf16 [n][k]
__device__ __align__(16) __nv_bfloat16 g_Wn[512 * 128];    // [W1a|W1b|srcW|selfW]^T bf16 [n][k]
__device__ float g_bn[512];                                 // 0|0|srcB|selfB

__device__ __forceinline__ float gelu_exact(float x) {
    return 0.5f * x * (1.0f + erff(x * 0.70710678118654752440f));
}
__device__ __forceinline__ uint32_t smem_u32(const void* p) {
    uint32_t a;
    asm("{ .reg .u64 t; cvta.to.shared.u64 t, %1; cvt.u32.u64 %0, t; }" : "=r"(a) : "l"(p));
    return a;
}
__device__ __forceinline__ void ldsm_x4(uint32_t* r, uint32_t addr) {
    asm volatile("ldmatrix.sync.aligned.m8n8.x4.shared.b16 {%0,%1,%2,%3}, [%4];"
                 : "=r"(r[0]), "=r"(r[1]), "=r"(r[2]), "=r"(r[3]) : "r"(addr));
}
__device__ __forceinline__ void ldsm_x2(uint32_t* r, uint32_t addr) {
    asm volatile("ldmatrix.sync.aligned.m8n8.x2.shared.b16 {%0,%1}, [%2];"
                 : "=r"(r[0]), "=r"(r[1]) : "r"(addr));
}
__device__ __forceinline__ void mma_bf16(float* c, const uint32_t* a, const uint32_t* b) {
    asm volatile(
        "mma.sync.aligned.m16n8k16.row.col.f32.bf16.bf16.f32 "
        "{%0,%1,%2,%3},{%4,%5,%6,%7},{%8,%9},{%0,%1,%2,%3};"
        : "+f"(c[0]), "+f"(c[1]), "+f"(c[2]), "+f"(c[3])
        : "r"(a[0]), "r"(a[1]), "r"(a[2]), "r"(a[3]), "r"(b[0]), "r"(b[1]));
}
__device__ __forceinline__ uint32_t pack_bf16(float a, float b) {
    __nv_bfloat162 t = __float22bfloat162_rn(make_float2(a, b));
    return *reinterpret_cast<uint32_t*>(&t);
}

// ---------------------------------------------------------------------------
// prep: W2^T bf16, Wnode^T bf16, node bias vector
// ---------------------------------------------------------------------------
__global__ void prep_kernel(const float* __restrict__ e2W,
                            const float* __restrict__ e1W,
                            const float* __restrict__ srcW,
                            const float* __restrict__ selfW,
                            const float* __restrict__ srcB,
                            const float* __restrict__ selfB) {
    int i = blockIdx.x * 256 + threadIdx.x;
    if (i < 512 * 128) {
        int n = i >> 7, k = i & 127;
        float v;
        if (n < 128)      v = e1W[k * 128 + n];
        else if (n < 256) v = e1W[(128 + k) * 128 + (n - 128)];
        else if (n < 384) v = srcW[k * 128 + (n - 256)];
        else              v = selfW[k * 128 + (n - 384)];
        g_Wn[i] = __float2bfloat16(v);
    }
    if (i < 256 * 128) {
        int n = i >> 7, k = i & 127;
        g_W2t[i] = __float2bfloat16(e2W[k * 256 + n]);
    }
    if (i < 512) {
        g_bn[i] = (i < 256) ? 0.0f : ((i < 384) ? srcB[i - 256] : selfB[i - 384]);
    }
}

// ---------------------------------------------------------------------------
__global__ void zero_kernel() {
    long i = (long)blockIdx.x * 256 + threadIdx.x;
    const long agg4 = (long)Nn * Hh / 4;
    if (i < agg4) ((float4*)g_agg)[i] = make_float4(0.f, 0.f, 0.f, 0.f);
    else if (i < agg4 + Nn / 4) ((float4*)g_indeg)[i - agg4] = make_float4(0.f, 0.f, 0.f, 0.f);
}

// ---------------------------------------------------------------------------
// K1: node projections via bf16 HMMA
//   [P1|P2|S|self](node, 512) = h(node,128) @ g_Wn^T + g_bn
// grid (391, 2): blockIdx.y = n-half (0: P1/P2, 1: S/self), 128 nodes/CTA.
// ---------------------------------------------------------------------------
#define NP_SM_A 0
#define NP_SM_B 32768
#define NP_SM_BI 98304
#define NP_SMEM 99328

__global__ void __launch_bounds__(256, 2)
node_pre_mma(const float* __restrict__ h) {
    extern __shared__ char smem[];
    const uint32_t sbm = smem_u32(smem);
    const int tid = threadIdx.x;
    const int lane = tid & 31;
    const int wid = tid >> 5;
    const int tile = blockIdx.x;
    const int half = blockIdx.y;
    float* bi_s = (float*)(smem + NP_SM_BI);

    // stage A (h tile -> bf16 swizzled)
#pragma unroll
    for (int it = 0; it < 8; it++) {
        int idx = tid + it * 256;          // 2048 chunks of 8 bf16
        int row = idx >> 4, c = idx & 15;
        int node = tile * 128 + row;
        uint4 w = make_uint4(0u, 0u, 0u, 0u);
        if (node < Nn) {
            const float4* p = (const float4*)(h + (long)node * 128 + c * 8);
            float4 v0 = p[0], v1 = p[1];
            w.x = pack_bf16(v0.x, v0.y); w.y = pack_bf16(v0.z, v0.w);
            w.z = pack_bf16(v1.x, v1.y); w.w = pack_bf16(v1.z, v1.w);
        }
        *(uint4*)(smem + NP_SM_A + row * 256 + ((c ^ (row & 7)) << 4)) = w;
    }
    // stage B (weight half, already [n][k] bf16)
#pragma unroll
    for (int it = 0; it < 16; it++) {
        int idx = tid + it * 256;          // 4096 chunks
        int n = idx >> 4, c = idx & 15;
        uint4 v = *(const uint4*)(g_Wn + (long)(half * 256 + n) * 128 + c * 8);
        *(uint4*)(smem + NP_SM_B + n * 256 + ((c ^ (n & 7)) << 4)) = v;
    }
    if (tid < 256) bi_s[tid] = g_bn[half * 256 + tid];
    __syncthreads();

    // A fragments (M=16 per warp)
    uint32_t Af[8][4];
    {
        int ts = lane >> 3;
        int row = wid * 16 + ((ts & 1) << 3) + (lane & 7);
        int rx = row & 7;
        uint32_t rb = sbm + NP_SM_A + row * 256;
#pragma unroll
        for (int kb = 0; kb < 8; kb++) {
            int c = kb * 2 + (ts >> 1);
            ldsm_x4(Af[kb], rb + ((c ^ rx) << 4));
        }
    }

    const int tsel = lane >> 3;
    const int jj_l = tsel >> 1;
    const int kh_l = tsel & 1;
    const int l7 = lane & 7;
    const int r0 = lane >> 2;
    const int cb2 = (lane & 3) * 2;

    // 16 pairs of n-tiles -> covers all 256 columns of this half
#pragma unroll 1
    for (int p = 0; p < 16; p++) {
        float C[2][4] = {{0.f,0.f,0.f,0.f},{0.f,0.f,0.f,0.f}};
        const int ng = p * 16 + jj_l * 8 + l7;     // rows (2p+jj)*8
#pragma unroll
        for (int kb = 0; kb < 8; kb++) {
            uint32_t Bf[4];
            int c = kb * 2 + kh_l;
            ldsm_x4(Bf, sbm + NP_SM_B + ng * 256 + ((c ^ (ng & 7)) << 4));
            mma_bf16(C[0], Af[kb], Bf);
            mma_bf16(C[1], Af[kb], Bf + 2);
        }
#pragma unroll
        for (int jj = 0; jj < 2; jj++) {
            int nl = (2 * p + jj) * 8 + cb2;           // 0..255 within half
            int n = half * 256 + nl;                   // 0..511
            float2 bias = *(const float2*)(bi_s + nl);
            float* dst = (n < 128) ? g_P1 : (n < 256) ? g_P2 : (n < 384) ? g_S : g_self;
            int nm = n & 127;
#pragma unroll
            for (int rh = 0; rh < 2; rh++) {
                int row = wid * 16 + r0 + rh * 8;
                int node = tile * 128 + row;
                if (node < Nn) {
                    float2 v = make_float2(C[jj][rh * 2] + bias.x, C[jj][rh * 2 + 1] + bias.y);
                    *(float2*)(dst + (long)node * 128 + nm) = v;
                }
            }
        }
    }
}

// ---------------------------------------------------------------------------
// K2: persistent edge kernel, EB=256, M=32/warp, back-to-back MMA.
// ---------------------------------------------------------------------------
#define SM_B2   0
#define SM_W1T  65536
#define SM_EST  69632
#define SM_B1   77824
#define SM_B2B  78336
#define SM_SRC  79360
#define SM_DST  80384
#define SMEM_EDGE 81408

__global__ void __launch_bounds__(256, 2)
edge_kernel(const float* __restrict__ eattr,
            const int* __restrict__ eidx,
            const float* __restrict__ e1W,
            const float* __restrict__ e1b,
            const float* __restrict__ e2b) {
    extern __shared__ char smem[];
    const uint32_t sbm = smem_u32(smem);
    const int tid = threadIdx.x;
    const int lane = tid & 31;
    const int wid = tid >> 5;
    float* b1_s = (float*)(smem + SM_B1);
    float* b2_s = (float*)(smem + SM_B2B);
    int* src_s  = (int*)(smem + SM_SRC);
    int* dst_s  = (int*)(smem + SM_DST);

    // one-time staging
#pragma unroll
    for (int it = 0; it < 16; it++) {
        int idx = tid + it * 256;
        int n = idx >> 4, c = idx & 15;
        uint4 v = *(const uint4*)(g_W2t + n * 128 + c * 8);
        *(uint4*)(smem + SM_B2 + n * 256 + ((c ^ (n & 7)) << 4)) = v;
    }
    for (int i = tid; i < 128 * 16; i += 256) {
        int n = i >> 4, k = i & 15;
        ((__nv_bfloat16*)(smem + SM_W1T))[n * 16 + k] =
            __float2bfloat16(e1W[(256 + k) * 128 + n]);
    }
    if (tid < 128) b1_s[tid] = e1b[tid];
    b2_s[tid] = e2b[tid];

    const int m0 = wid * 32;
    const int r0 = lane >> 2;
    const int cbase = (lane & 3) * 2;
    const int tl8 = lane & 15;
    const int tsel = lane >> 3;
    const int jj_l = tsel >> 1;
    const int kh_l = tsel & 1;
    const int l7 = lane & 7;

    for (int tile = blockIdx.x; tile < NT; tile += EGRID) {
        const long eb = (long)tile * EB;
        const int remaining = (int)(Ee - eb);
        __syncthreads();

        {   // stage indices + eattr (each thread: one edge)
            long e = eb + tid;
            int s = 0, d = 0;
            if (tid < remaining) {
                s = eidx[2 * e];
                d = eidx[2 * e + 1];
                atomicAdd(&g_indeg[d], 1.0f);
            }
            src_s[tid] = s;
            dst_s[tid] = d;
            long ec = (tid < remaining) ? e : eb;
            const float4* p = (const float4*)(eattr + ec * 16);
            float4 v0 = p[0], v1 = p[1], v2 = p[2], v3 = p[3];
            uint4 w0, w1;
            w0.x = pack_bf16(v0.x, v0.y); w0.y = pack_bf16(v0.z, v0.w);
            w0.z = pack_bf16(v1.x, v1.y); w0.w = pack_bf16(v1.z, v1.w);
            w1.x = pack_bf16(v2.x, v2.y); w1.y = pack_bf16(v2.z, v2.w);
            w1.z = pack_bf16(v3.x, v3.y); w1.w = pack_bf16(v3.z, v3.w);
            *(uint4*)(smem + SM_EST + tid * 32) = w0;
            *(uint4*)(smem + SM_EST + tid * 32 + 16) = w1;
        }
        __syncthreads();

        // ---- hid for 2 M-tiles: C1 init + MMA1 + gelu -> A2 frags ----
        uint32_t A2[2][8][4];
#pragma unroll 1
        for (int mt = 0; mt < 2; mt++) {
            const int rowA = m0 + mt * 16 + r0;
            const int rowB = rowA + 8;
            const int sa = src_s[rowA], da = dst_s[rowA];
            const int sb2 = src_s[rowB], db = dst_s[rowB];
            const float* p1a = g_P1 + (long)sa * Hh;
            const float* p2a = g_P2 + (long)da * Hh;
            const float* p1b = g_P1 + (long)sb2 * Hh;
            const float* p2b = g_P2 + (long)db * Hh;

            float C1[16][4];
#pragma unroll
            for (int j = 0; j < 16; j++) {
                int c = j * 8 + cbase;
                float2 x1 = *(const float2*)(p1a + c);
                float2 x2 = *(const float2*)(p2a + c);
                float2 y1 = *(const float2*)(p1b + c);
                float2 y2 = *(const float2*)(p2b + c);
                float2 bb = *(const float2*)(b1_s + c);
                C1[j][0] = x1.x + x2.x + bb.x;
                C1[j][1] = x1.y + x2.y + bb.y;
                C1[j][2] = y1.x + y2.x + bb.x;
                C1[j][3] = y1.y + y2.y + bb.y;
            }
            uint32_t A1[4];
            {
                int row = m0 + mt * 16 + ((tsel & 1) << 3) + l7;
                ldsm_x4(A1, sbm + SM_EST + row * 32 + ((tsel >> 1) << 4));
            }
#pragma unroll
            for (int j = 0; j < 16; j++) {
                uint32_t Bf[2];
                int n = j * 8 + (tl8 & 7);
                ldsm_x2(Bf, sbm + SM_W1T + n * 32 + ((tl8 >> 3) << 4));
                mma_bf16(C1[j], A1, Bf);
            }
#pragma unroll
            for (int kb = 0; kb < 8; kb++) {
                A2[mt][kb][0] = pack_bf16(gelu_exact(C1[2 * kb][0]),     gelu_exact(C1[2 * kb][1]));
                A2[mt][kb][1] = pack_bf16(gelu_exact(C1[2 * kb][2]),     gelu_exact(C1[2 * kb][3]));
                A2[mt][kb][2] = pack_bf16(gelu_exact(C1[2 * kb + 1][0]), gelu_exact(C1[2 * kb + 1][1]));
                A2[mt][kb][3] = pack_bf16(gelu_exact(C1[2 * kb + 1][2]), gelu_exact(C1[2 * kb + 1][3]));
            }
        }

        // ---- MMA2 + fused epilogue ----
#pragma unroll 1
        for (int g = 0; g < 8; g++) {
            float Cg[2][2][4] = {}, Cs[2][2][4] = {};
            const int ngl = (2 * g + jj_l) * 8 + l7;
            const int nsl = ngl + 128;
#pragma unroll
            for (int kb = 0; kb < 8; kb++) {
                uint32_t Bg[4], Bs[4];
                int c = kb * 2 + kh_l;
                ldsm_x4(Bg, sbm + SM_B2 + ngl * 256 + ((c ^ (ngl & 7)) << 4));
                ldsm_x4(Bs, sbm + SM_B2 + nsl * 256 + ((c ^ (nsl & 7)) << 4));
#pragma unroll
                for (int mt = 0; mt < 2; mt++) {
                    mma_bf16(Cg[mt][0], A2[mt][kb], Bg);
                    mma_bf16(Cg[mt][1], A2[mt][kb], Bg + 2);
                    mma_bf16(Cs[mt][0], A2[mt][kb], Bs);
                    mma_bf16(Cs[mt][1], A2[mt][kb], Bs + 2);
                }
            }
#pragma unroll
            for (int mt = 0; mt < 2; mt++) {
#pragma unroll
                for (int jj = 0; jj < 2; jj++) {
                    int c0 = (2 * g + jj) * 8 + cbase;
                    float2 bg = *(const float2*)(b2_s + c0);
                    float2 bsv = *(const float2*)(b2_s + 128 + c0);
#pragma unroll
                    for (int rh = 0; rh < 2; rh++) {
                        int row = m0 + mt * 16 + rh * 8 + r0;
                        if (row < remaining) {
                            int s = src_s[row], d = dst_s[row];
                            float2 sv = *(const float2*)(g_S + (long)s * Hh + c0);
                            float g0 = Cg[mt][jj][rh * 2]     + bg.x;
                            float g1 = Cg[mt][jj][rh * 2 + 1] + bg.y;
                            float s0 = Cs[mt][jj][rh * 2]     + bsv.x;
                            float s1 = Cs[mt][jj][rh * 2 + 1] + bsv.y;
                            float v0 = sv.x * __fdividef(1.0f, 1.0f + __expf(-g0)) + s0;
                            float v1 = sv.y * __fdividef(1.0f, 1.0f + __expf(-g1)) + s1;
                            asm volatile("red.global.add.v2.f32 [%0], {%1,%2};"
                                         :: "l"(g_agg + (long)d * Hh + c0), "f"(v0), "f"(v1)
                                         : "memory");
                        }
                    }
                }
            }
        }
    }
}

// ---------------------------------------------------------------------------
// K3: node update + residual GELU + LayerNorm (8 nodes / block)
// ---------------------------------------------------------------------------
__global__ void node_update_kernel(const float* __restrict__ h,
                                   const float* __restrict__ aggW,
                                   const float* __restrict__ aggB,
                                   const float* __restrict__ lng,
                                   const float* __restrict__ lnb,
                                   float* __restrict__ out) {
    __shared__ float sA[8][Hh];
    __shared__ float sX[8][Hh];

    const int tid = threadIdx.x;
    const int nb = blockIdx.x * 8;

#pragma unroll
    for (int i = 0; i < 8; i++) {
        int n = nb + i;
        if (n < Nn) {
            float rd = 1.0f / fmaxf(g_indeg[n], 1.0f);
            sA[i][tid] = g_agg[(long)n * Hh + tid] * rd;
        } else sA[i][tid] = 0.0f;
    }
    __syncthreads();

    float acc[8] = {};
#pragma unroll 4
    for (int k = 0; k < Hh; k++) {
        float w = __ldg(aggW + k * Hh + tid);
#pragma unroll
        for (int i = 0; i < 8; i++) acc[i] += sA[i][k] * w;
    }
    float ab = __ldg(aggB + tid);
#pragma unroll
    for (int i = 0; i < 8; i++) {
        int n = nb + i;
        if (n < Nn) {
            float u = g_self[(long)n * Hh + tid] + acc[i] + ab;
            sX[i][tid] = h[(long)n * Hh + tid] + gelu_exact(u);
        }
    }
    __syncthreads();

    const int wid = tid >> 5, lane = tid & 31;
#pragma unroll
    for (int pass = 0; pass < 2; pass++) {
        int ni = wid + pass * 4;
        int n = nb + ni;
        if (n < Nn) {
            float v[4], sm = 0.f, s2 = 0.f;
#pragma unroll
            for (int r = 0; r < 4; r++) {
                v[r] = sX[ni][lane + 32 * r];
                sm += v[r];
                s2 += v[r] * v[r];
            }
#pragma unroll
            for (int o = 16; o > 0; o >>= 1) {
                sm += __shfl_xor_sync(0xffffffff, sm, o);
                s2 += __shfl_xor_sync(0xffffffff, s2, o);
            }
            float mu = sm * (1.0f / Hh);
            float var = s2 * (1.0f / Hh) - mu * mu;
            float rstd = rsqrtf(var + LN_EPS);
#pragma unroll
            for (int r = 0; r < 4; r++) {
                int j = lane + 32 * r;
                out[(long)n * Hh + j] = (v[r] - mu) * rstd * __ldg(lng + j) + __ldg(lnb + j);
            }
        }
    }
}

// ---------------------------------------------------------------------------
extern "C" void kernel_launch(void* const* d_in, const int* in_sizes, int n_in,
                              void* d_out, int out_size) {
    const float* h     = (const float*)d_in[0];
    const float* eattr = (const float*)d_in[1];
    const int*   eidx  = (const int*)d_in[2];
    const float* srcW  = (const float*)d_in[3];
    const float* srcB  = (const float*)d_in[4];
    const float* e1W   = (const float*)d_in[5];
    const float* e1b   = (const float*)d_in[6];
    const float* e2W   = (const float*)d_in[7];
    const float* e2b   = (const float*)d_in[8];
    const float* selfW = (const float*)d_in[9];
    const float* selfB = (const float*)d_in[10];
    const float* aggW  = (const float*)d_in[11];
    const float* aggB  = (const float*)d_in[12];
    const float* lng   = (const float*)d_in[13];
    const float* lnb   = (const float*)d_in[14];
    float* out = (float*)d_out;

    cudaFuncSetAttribute(edge_kernel, cudaFuncAttributeMaxDynamicSharedMemorySize, SMEM_EDGE);
    cudaFuncSetAttribute(node_pre_mma, cudaFuncAttributeMaxDynamicSharedMemorySize, NP_SMEM);

    long zero_elems = (long)Nn * Hh / 4 + Nn / 4;
    zero_kernel<<<(int)((zero_elems + 255) / 256), 256>>>();
    prep_kernel<<<256, 256>>>(e2W, e1W, srcW, selfW, srcB, selfB);
    node_pre_mma<<<dim3((Nn + 127) / 128, 2), 256, NP_SMEM>>>(h);
    edge_kernel<<<EGRID, 256, SMEM_EDGE>>>(eattr, eidx, e1W, e1b, e2b);
    node_update_kernel<<<(Nn + 7) / 8, 128>>>(h, aggW, aggB, lng, lnb, out);
}

// round 7
// speedup vs baseline: 4.5583x; 1.1993x over previous
#include <cuda_runtime.h>
#include <cuda_bf16.h>
#include <math.h>
#include <cstdint>

#define Hh 128
#define Nn 50000
#define Ee 500000
#define LN_EPS 1e-5f
#define EB 128
#define NT ((Ee + EB - 1) / EB)     // 3907 tiles
#define EGRID 296

// ---------------- scratch ----------------
__device__ float g_P1[Nn * Hh];
__device__ float g_P2[Nn * Hh];
__device__ float g_S[Nn * Hh];
__device__ float g_self[Nn * Hh];
__device__ float g_agg[Nn * Hh];
__device__ float g_indeg[Nn];
__device__ __align__(16) __nv_bfloat16 g_W2t[256 * 128];   // W2^T bf16 [n][k]
__device__ __align__(16) __nv_bfloat16 g_Wn[512 * 128];    // [W1a|W1b|srcW|selfW]^T bf16 [n][k]
__device__ float g_bn[512];                                 // 0|0|srcB|selfB

__device__ __forceinline__ float gelu_exact(float x) {
    return 0.5f * x * (1.0f + erff(x * 0.70710678118654752440f));
}
__device__ __forceinline__ uint32_t smem_u32(const void* p) {
    uint32_t a;
    asm("{ .reg .u64 t; cvta.to.shared.u64 t, %1; cvt.u32.u64 %0, t; }" : "=r"(a) : "l"(p));
    return a;
}
__device__ __forceinline__ void ldsm_x4(uint32_t* r, uint32_t addr) {
    asm volatile("ldmatrix.sync.aligned.m8n8.x4.shared.b16 {%0,%1,%2,%3}, [%4];"
                 : "=r"(r[0]), "=r"(r[1]), "=r"(r[2]), "=r"(r[3]) : "r"(addr));
}
__device__ __forceinline__ void ldsm_x2(uint32_t* r, uint32_t addr) {
    asm volatile("ldmatrix.sync.aligned.m8n8.x2.shared.b16 {%0,%1}, [%2];"
                 : "=r"(r[0]), "=r"(r[1]) : "r"(addr));
}
__device__ __forceinline__ void mma_bf16(float* c, const uint32_t* a, const uint32_t* b) {
    asm volatile(
        "mma.sync.aligned.m16n8k16.row.col.f32.bf16.bf16.f32 "
        "{%0,%1,%2,%3},{%4,%5,%6,%7},{%8,%9},{%0,%1,%2,%3};"
        : "+f"(c[0]), "+f"(c[1]), "+f"(c[2]), "+f"(c[3])
        : "r"(a[0]), "r"(a[1]), "r"(a[2]), "r"(a[3]), "r"(b[0]), "r"(b[1]));
}
__device__ __forceinline__ uint32_t pack_bf16(float a, float b) {
    __nv_bfloat162 t = __float22bfloat162_rn(make_float2(a, b));
    return *reinterpret_cast<uint32_t*>(&t);
}

// ---------------------------------------------------------------------------
// prep: W2^T bf16, Wnode^T bf16, node bias vector
// ---------------------------------------------------------------------------
__global__ void prep_kernel(const float* __restrict__ e2W,
                            const float* __restrict__ e1W,
                            const float* __restrict__ srcW,
                            const float* __restrict__ selfW,
                            const float* __restrict__ srcB,
                            const float* __restrict__ selfB) {
    int i = blockIdx.x * 256 + threadIdx.x;
    if (i < 512 * 128) {
        int n = i >> 7, k = i & 127;
        float v;
        if (n < 128)      v = e1W[k * 128 + n];
        else if (n < 256) v = e1W[(128 + k) * 128 + (n - 128)];
        else if (n < 384) v = srcW[k * 128 + (n - 256)];
        else              v = selfW[k * 128 + (n - 384)];
        g_Wn[i] = __float2bfloat16(v);
    }
    if (i < 256 * 128) {
        int n = i >> 7, k = i & 127;
        g_W2t[i] = __float2bfloat16(e2W[k * 256 + n]);
    }
    if (i < 512) {
        g_bn[i] = (i < 256) ? 0.0f : ((i < 384) ? srcB[i - 256] : selfB[i - 384]);
    }
}

// ---------------------------------------------------------------------------
__global__ void zero_kernel() {
    long i = (long)blockIdx.x * 256 + threadIdx.x;
    const long agg4 = (long)Nn * Hh / 4;
    if (i < agg4) ((float4*)g_agg)[i] = make_float4(0.f, 0.f, 0.f, 0.f);
    else if (i < agg4 + Nn / 4) ((float4*)g_indeg)[i - agg4] = make_float4(0.f, 0.f, 0.f, 0.f);
}

// ---------------------------------------------------------------------------
// K1: node projections via bf16 HMMA
//   [P1|P2|S|self](node, 512) = h(node,128) @ g_Wn^T + g_bn
// ---------------------------------------------------------------------------
#define NP_SM_A 0
#define NP_SM_B 32768
#define NP_SM_BI 98304
#define NP_SMEM 99328

__global__ void __launch_bounds__(256, 2)
node_pre_mma(const float* __restrict__ h) {
    extern __shared__ char smem[];
    const uint32_t sbm = smem_u32(smem);
    const int tid = threadIdx.x;
    const int lane = tid & 31;
    const int wid = tid >> 5;
    const int tile = blockIdx.x;
    const int half = blockIdx.y;
    float* bi_s = (float*)(smem + NP_SM_BI);

#pragma unroll
    for (int it = 0; it < 8; it++) {
        int idx = tid + it * 256;
        int row = idx >> 4, c = idx & 15;
        int node = tile * 128 + row;
        uint4 w = make_uint4(0u, 0u, 0u, 0u);
        if (node < Nn) {
            const float4* p = (const float4*)(h + (long)node * 128 + c * 8);
            float4 v0 = p[0], v1 = p[1];
            w.x = pack_bf16(v0.x, v0.y); w.y = pack_bf16(v0.z, v0.w);
            w.z = pack_bf16(v1.x, v1.y); w.w = pack_bf16(v1.z, v1.w);
        }
        *(uint4*)(smem + NP_SM_A + row * 256 + ((c ^ (row & 7)) << 4)) = w;
    }
#pragma unroll
    for (int it = 0; it < 16; it++) {
        int idx = tid + it * 256;
        int n = idx >> 4, c = idx & 15;
        uint4 v = *(const uint4*)(g_Wn + (long)(half * 256 + n) * 128 + c * 8);
        *(uint4*)(smem + NP_SM_B + n * 256 + ((c ^ (n & 7)) << 4)) = v;
    }
    if (tid < 256) bi_s[tid] = g_bn[half * 256 + tid];
    __syncthreads();

    uint32_t Af[8][4];
    {
        int ts = lane >> 3;
        int row = wid * 16 + ((ts & 1) << 3) + (lane & 7);
        int rx = row & 7;
        uint32_t rb = sbm + NP_SM_A + row * 256;
#pragma unroll
        for (int kb = 0; kb < 8; kb++) {
            int c = kb * 2 + (ts >> 1);
            ldsm_x4(Af[kb], rb + ((c ^ rx) << 4));
        }
    }

    const int tsel = lane >> 3;
    const int jj_l = tsel >> 1;
    const int kh_l = tsel & 1;
    const int l7 = lane & 7;
    const int r0 = lane >> 2;
    const int cb2 = (lane & 3) * 2;

#pragma unroll 1
    for (int p = 0; p < 16; p++) {
        float C[2][4] = {{0.f,0.f,0.f,0.f},{0.f,0.f,0.f,0.f}};
        const int ng = p * 16 + jj_l * 8 + l7;
#pragma unroll
        for (int kb = 0; kb < 8; kb++) {
            uint32_t Bf[4];
            int c = kb * 2 + kh_l;
            ldsm_x4(Bf, sbm + NP_SM_B + ng * 256 + ((c ^ (ng & 7)) << 4));
            mma_bf16(C[0], Af[kb], Bf);
            mma_bf16(C[1], Af[kb], Bf + 2);
        }
#pragma unroll
        for (int jj = 0; jj < 2; jj++) {
            int nl = (2 * p + jj) * 8 + cb2;
            int n = half * 256 + nl;
            float2 bias = *(const float2*)(bi_s + nl);
            float* dst = (n < 128) ? g_P1 : (n < 256) ? g_P2 : (n < 384) ? g_S : g_self;
            int nm = n & 127;
#pragma unroll
            for (int rh = 0; rh < 2; rh++) {
                int row = wid * 16 + r0 + rh * 8;
                int node = tile * 128 + row;
                if (node < Nn) {
                    float2 v = make_float2(C[jj][rh * 2] + bias.x, C[jj][rh * 2 + 1] + bias.y);
                    *(float2*)(dst + (long)node * 128 + nm) = v;
                }
            }
        }
    }
}

// ---------------------------------------------------------------------------
// K2: persistent edge kernel, EB=128, M=16/warp (R4 shape) + x4 B-loads.
// smem:
//   B2    [256n x 128k bf16, 256B/row XOR-swz]  @ 0       (65536)
//   W1T   [128n x 16k bf16, 32B/row]            @ 65536   (4096)
//   EST   [128e x 16 bf16, 32B/row]             @ 69632   (4096)
//   b1    [128 f32]                             @ 73728   (512)
//   b2    [256 f32]                             @ 74240   (1024)
//   src   [128 i32]                             @ 75264   (512)
//   dst   [128 i32]                             @ 75776   (512)
#define SM_B2   0
#define SM_W1T  65536
#define SM_EST  69632
#define SM_B1   73728
#define SM_B2B  74240
#define SM_SRC  75264
#define SM_DST  75776
#define SMEM_EDGE 76288

__global__ void __launch_bounds__(256, 2)
edge_kernel(const float* __restrict__ eattr,
            const int* __restrict__ eidx,
            const float* __restrict__ e1W,
            const float* __restrict__ e1b,
            const float* __restrict__ e2b) {
    extern __shared__ char smem[];
    const uint32_t sbm = smem_u32(smem);
    const int tid = threadIdx.x;
    const int lane = tid & 31;
    const int wid = tid >> 5;           // 0..7, warp owns rows wid*16..+15
    float* b1_s = (float*)(smem + SM_B1);
    float* b2_s = (float*)(smem + SM_B2B);
    int* src_s  = (int*)(smem + SM_SRC);
    int* dst_s  = (int*)(smem + SM_DST);

    // ---- one-time staging ----
#pragma unroll
    for (int it = 0; it < 16; it++) {
        int idx = tid + it * 256;
        int n = idx >> 4, c = idx & 15;
        uint4 v = *(const uint4*)(g_W2t + n * 128 + c * 8);
        *(uint4*)(smem + SM_B2 + n * 256 + ((c ^ (n & 7)) << 4)) = v;
    }
    for (int i = tid; i < 128 * 16; i += 256) {
        int n = i >> 4, k = i & 15;
        ((__nv_bfloat16*)(smem + SM_W1T))[n * 16 + k] =
            __float2bfloat16(e1W[(256 + k) * 128 + n]);
    }
    if (tid < 128) b1_s[tid] = e1b[tid];
    b2_s[tid & 255] = e2b[tid & 255];

    const int m0 = wid * 16;
    const int r0 = lane >> 2;
    const int rowA = m0 + r0, rowB = rowA + 8;
    const int cbase = (lane & 3) * 2;
    const int tl8 = lane & 15;
    const int tsel = lane >> 3;
    const int jj_l = tsel >> 1;
    const int kh_l = tsel & 1;
    const int l7 = lane & 7;

    for (int tile = blockIdx.x; tile < NT; tile += EGRID) {
        const long eb = (long)tile * EB;
        const int remaining = (int)(Ee - eb);
        __syncthreads();

        if (tid < 128) {
            long e = eb + tid;
            int s = 0, d = 0;
            if (tid < remaining) {
                s = eidx[2 * e];
                d = eidx[2 * e + 1];
                atomicAdd(&g_indeg[d], 1.0f);
            }
            src_s[tid] = s;
            dst_s[tid] = d;
        }
        {   // stage eattr bf16: 2 threads per edge
            int erow = tid >> 1;
            long e = eb + erow;
            long ec = (erow < remaining) ? e : eb;
            const float4* p = (const float4*)(eattr + ec * 16 + (tid & 1) * 8);
            float4 v0 = p[0], v1 = p[1];
            uint4 w;
            w.x = pack_bf16(v0.x, v0.y); w.y = pack_bf16(v0.z, v0.w);
            w.z = pack_bf16(v1.x, v1.y); w.w = pack_bf16(v1.z, v1.w);
            *(uint4*)(smem + SM_EST + erow * 32 + (tid & 1) * 16) = w;
        }
        __syncthreads();

        const int sa = src_s[rowA], da = dst_s[rowA];
        const int sb2 = src_s[rowB], db = dst_s[rowB];
        const float* p1a = g_P1 + (long)sa * Hh;
        const float* p2a = g_P2 + (long)da * Hh;
        const float* p1b = g_P1 + (long)sb2 * Hh;
        const float* p2b = g_P2 + (long)db * Hh;

        // ---- C1 init = P1[s] + P2[d] + b1 (C fragment layout) ----
        float C1[16][4];
#pragma unroll
        for (int j = 0; j < 16; j++) {
            int c = j * 8 + cbase;
            float2 x1 = *(const float2*)(p1a + c);
            float2 x2 = *(const float2*)(p2a + c);
            float2 y1 = *(const float2*)(p1b + c);
            float2 y2 = *(const float2*)(p2b + c);
            float2 bb = *(const float2*)(b1_s + c);
            C1[j][0] = x1.x + x2.x + bb.x;
            C1[j][1] = x1.y + x2.y + bb.y;
            C1[j][2] = y1.x + y2.x + bb.x;
            C1[j][3] = y1.y + y2.y + bb.y;
        }

        // ---- MMA1: C1 += eattr(16) @ W1e(16x128) ----
        uint32_t A1[4];
        {
            int row = m0 + ((tsel & 1) << 3) + l7;
            ldsm_x4(A1, sbm + SM_EST + row * 32 + ((tsel >> 1) << 4));
        }
#pragma unroll
        for (int j = 0; j < 16; j++) {
            uint32_t Bf[2];
            int n = j * 8 + (tl8 & 7);
            ldsm_x2(Bf, sbm + SM_W1T + n * 32 + ((tl8 >> 3) << 4));
            mma_bf16(C1[j], A1, Bf);
        }

        // ---- GELU + repack C1 -> A2 fragments ----
        uint32_t A2[8][4];
#pragma unroll
        for (int kb = 0; kb < 8; kb++) {
            A2[kb][0] = pack_bf16(gelu_exact(C1[2 * kb][0]),     gelu_exact(C1[2 * kb][1]));
            A2[kb][1] = pack_bf16(gelu_exact(C1[2 * kb][2]),     gelu_exact(C1[2 * kb][3]));
            A2[kb][2] = pack_bf16(gelu_exact(C1[2 * kb + 1][0]), gelu_exact(C1[2 * kb + 1][1]));
            A2[kb][3] = pack_bf16(gelu_exact(C1[2 * kb + 1][2]), gelu_exact(C1[2 * kb + 1][3]));
        }

        // ---- MMA2 + fused epilogue, 8 groups of 16 cols (x4 B-loads) ----
        const bool va = (rowA < remaining), vb = (rowB < remaining);
        const float* Spa = g_S + (long)sa * Hh;
        const float* Spb = g_S + (long)sb2 * Hh;
        float* apa = g_agg + (long)da * Hh;
        float* apb = g_agg + (long)db * Hh;

#pragma unroll 1
        for (int g = 0; g < 8; g++) {
            float Cg[2][4] = {}, Cs[2][4] = {};
            const int ngl = (2 * g + jj_l) * 8 + l7;
            const int nsl = ngl + 128;
#pragma unroll
            for (int kb = 0; kb < 8; kb++) {
                uint32_t Bg[4], Bs[4];
                int c = kb * 2 + kh_l;
                ldsm_x4(Bg, sbm + SM_B2 + ngl * 256 + ((c ^ (ngl & 7)) << 4));
                ldsm_x4(Bs, sbm + SM_B2 + nsl * 256 + ((c ^ (nsl & 7)) << 4));
                mma_bf16(Cg[0], A2[kb], Bg);
                mma_bf16(Cg[1], A2[kb], Bg + 2);
                mma_bf16(Cs[0], A2[kb], Bs);
                mma_bf16(Cs[1], A2[kb], Bs + 2);
            }
#pragma unroll
            for (int jj = 0; jj < 2; jj++) {
                int c0 = (2 * g + jj) * 8 + cbase;
                float2 bg = *(const float2*)(b2_s + c0);
                float2 bsv = *(const float2*)(b2_s + 128 + c0);
                if (va) {
                    float2 sv = *(const float2*)(Spa + c0);
                    float g0 = Cg[jj][0] + bg.x, g1 = Cg[jj][1] + bg.y;
                    float s0 = Cs[jj][0] + bsv.x, s1 = Cs[jj][1] + bsv.y;
                    float v0 = sv.x * __fdividef(1.0f, 1.0f + __expf(-g0)) + s0;
                    float v1 = sv.y * __fdividef(1.0f, 1.0f + __expf(-g1)) + s1;
                    asm volatile("red.global.add.v2.f32 [%0], {%1,%2};"
                                 :: "l"(apa + c0), "f"(v0), "f"(v1) : "memory");
                }
                if (vb) {
                    float2 sv = *(const float2*)(Spb + c0);
                    float g0 = Cg[jj][2] + bg.x, g1 = Cg[jj][3] + bg.y;
                    float s0 = Cs[jj][2] + bsv.x, s1 = Cs[jj][3] + bsv.y;
                    float v0 = sv.x * __fdividef(1.0f, 1.0f + __expf(-g0)) + s0;
                    float v1 = sv.y * __fdividef(1.0f, 1.0f + __expf(-g1)) + s1;
                    asm volatile("red.global.add.v2.f32 [%0], {%1,%2};"
                                 :: "l"(apb + c0), "f"(v0), "f"(v1) : "memory");
                }
            }
        }
    }
}

// ---------------------------------------------------------------------------
// K3: node update + residual GELU + LayerNorm (8 nodes / block)
// ---------------------------------------------------------------------------
__global__ void node_update_kernel(const float* __restrict__ h,
                                   const float* __restrict__ aggW,
                                   const float* __restrict__ aggB,
                                   const float* __restrict__ lng,
                                   const float* __restrict__ lnb,
                                   float* __restrict__ out) {
    __shared__ float sA[8][Hh];
    __shared__ float sX[8][Hh];

    const int tid = threadIdx.x;
    const int nb = blockIdx.x * 8;

#pragma unroll
    for (int i = 0; i < 8; i++) {
        int n = nb + i;
        if (n < Nn) {
            float rd = 1.0f / fmaxf(g_indeg[n], 1.0f);
            sA[i][tid] = g_agg[(long)n * Hh + tid] * rd;
        } else sA[i][tid] = 0.0f;
    }
    __syncthreads();

    float acc[8] = {};
#pragma unroll 4
    for (int k = 0; k < Hh; k++) {
        float w = __ldg(aggW + k * Hh + tid);
#pragma unroll
        for (int i = 0; i < 8; i++) acc[i] += sA[i][k] * w;
    }
    float ab = __ldg(aggB + tid);
#pragma unroll
    for (int i = 0; i < 8; i++) {
        int n = nb + i;
        if (n < Nn) {
            float u = g_self[(long)n * Hh + tid] + acc[i] + ab;
            sX[i][tid] = h[(long)n * Hh + tid] + gelu_exact(u);
        }
    }
    __syncthreads();

    const int wid = tid >> 5, lane = tid & 31;
#pragma unroll
    for (int pass = 0; pass < 2; pass++) {
        int ni = wid + pass * 4;
        int n = nb + ni;
        if (n < Nn) {
            float v[4], sm = 0.f, s2 = 0.f;
#pragma unroll
            for (int r = 0; r < 4; r++) {
                v[r] = sX[ni][lane + 32 * r];
                sm += v[r];
                s2 += v[r] * v[r];
            }
#pragma unroll
            for (int o = 16; o > 0; o >>= 1) {
                sm += __shfl_xor_sync(0xffffffff, sm, o);
                s2 += __shfl_xor_sync(0xffffffff, s2, o);
            }
            float mu = sm * (1.0f / Hh);
            float var = s2 * (1.0f / Hh) - mu * mu;
            float rstd = rsqrtf(var + LN_EPS);
#pragma unroll
            for (int r = 0; r < 4; r++) {
                int j = lane + 32 * r;
                out[(long)n * Hh + j] = (v[r] - mu) * rstd * __ldg(lng + j) + __ldg(lnb + j);
            }
        }
    }
}

// ---------------------------------------------------------------------------
extern "C" void kernel_launch(void* const* d_in, const int* in_sizes, int n_in,
                              void* d_out, int out_size) {
    const float* h     = (const float*)d_in[0];
    const float* eattr = (const float*)d_in[1];
    const int*   eidx  = (const int*)d_in[2];
    const float* srcW  = (const float*)d_in[3];
    const float* srcB  = (const float*)d_in[4];
    const float* e1W   = (const float*)d_in[5];
    const float* e1b   = (const float*)d_in[6];
    const float* e2W   = (const float*)d_in[7];
    const float* e2b   = (const float*)d_in[8];
    const float* selfW = (const float*)d_in[9];
    const float* selfB = (const float*)d_in[10];
    const float* aggW  = (const float*)d_in[11];
    const float* aggB  = (const float*)d_in[12];
    const float* lng   = (const float*)d_in[13];
    const float* lnb   = (const float*)d_in[14];
    float* out = (float*)d_out;

    cudaFuncSetAttribute(edge_kernel, cudaFuncAttributeMaxDynamicSharedMemorySize, SMEM_EDGE);
    cudaFuncSetAttribute(node_pre_mma, cudaFuncAttributeMaxDynamicSharedMemorySize, NP_SMEM);

    long zero_elems = (long)Nn * Hh / 4 + Nn / 4;
    zero_kernel<<<(int)((zero_elems + 255) / 256), 256>>>();
    prep_kernel<<<256, 256>>>(e2W, e1W, srcW, selfW, srcB, selfB);
    node_pre_mma<<<dim3((Nn + 127) / 128, 2), 256, NP_SMEM>>>(h);
    edge_kernel<<<EGRID, 256, SMEM_EDGE>>>(eattr, eidx, e1W, e1b, e2b);
    node_update_kernel<<<(Nn + 7) / 8, 128>>>(h, aggW, aggB, lng, lnb, out);
}

// round 8
// speedup vs baseline: 4.9624x; 1.0887x over previous
#include <cuda_runtime.h>
#include <cuda_bf16.h>
#include <math.h>
#include <cstdint>

#define Hh 128
#define Nn 50000
#define Ee 500000
#define LN_EPS 1e-5f
#define EB 128
#define NT ((Ee + EB - 1) / EB)     // 3907 tiles
#define EGRID 296

// ---------------- scratch ----------------
__device__ __align__(16) __nv_bfloat16 g_P1b[Nn * Hh];   // h @ e1_W[0:128], bf16
__device__ __align__(16) __nv_bfloat16 g_P2b[Nn * Hh];   // h @ e1_W[128:256], bf16
__device__ __align__(16) __nv_bfloat16 g_Sb[Nn * Hh];    // h @ src_W + src_b, bf16
__device__ float g_self[Nn * Hh];                         // h @ self_W + self_b
__device__ float g_agg[Nn * Hh];
__device__ float g_indeg[Nn];
__device__ __align__(16) __nv_bfloat16 g_W2t[256 * 128]; // W2^T bf16 [n][k]
__device__ __align__(16) __nv_bfloat16 g_Wn[512 * 128];  // [W1a|W1b|srcW|selfW]^T bf16
__device__ float g_bn[512];                               // 0|0|srcB|selfB

__device__ __forceinline__ float gelu_exact(float x) {
    return 0.5f * x * (1.0f + erff(x * 0.70710678118654752440f));
}
__device__ __forceinline__ uint32_t smem_u32(const void* p) {
    uint32_t a;
    asm("{ .reg .u64 t; cvta.to.shared.u64 t, %1; cvt.u32.u64 %0, t; }" : "=r"(a) : "l"(p));
    return a;
}
__device__ __forceinline__ void ldsm_x4(uint32_t* r, uint32_t addr) {
    asm volatile("ldmatrix.sync.aligned.m8n8.x4.shared.b16 {%0,%1,%2,%3}, [%4];"
                 : "=r"(r[0]), "=r"(r[1]), "=r"(r[2]), "=r"(r[3]) : "r"(addr));
}
__device__ __forceinline__ void ldsm_x2(uint32_t* r, uint32_t addr) {
    asm volatile("ldmatrix.sync.aligned.m8n8.x2.shared.b16 {%0,%1}, [%2];"
                 : "=r"(r[0]), "=r"(r[1]) : "r"(addr));
}
__device__ __forceinline__ void mma_bf16(float* c, const uint32_t* a, const uint32_t* b) {
    asm volatile(
        "mma.sync.aligned.m16n8k16.row.col.f32.bf16.bf16.f32 "
        "{%0,%1,%2,%3},{%4,%5,%6,%7},{%8,%9},{%0,%1,%2,%3};"
        : "+f"(c[0]), "+f"(c[1]), "+f"(c[2]), "+f"(c[3])
        : "r"(a[0]), "r"(a[1]), "r"(a[2]), "r"(a[3]), "r"(b[0]), "r"(b[1]));
}
__device__ __forceinline__ uint32_t pack_bf16(float a, float b) {
    __nv_bfloat162 t = __float22bfloat162_rn(make_float2(a, b));
    return *reinterpret_cast<uint32_t*>(&t);
}
__device__ __forceinline__ float2 bf2f(const __nv_bfloat16* p) {
    return __bfloat1622float2(*(const __nv_bfloat162*)p);
}

// ---------------------------------------------------------------------------
__global__ void prep_kernel(const float* __restrict__ e2W,
                            const float* __restrict__ e1W,
                            const float* __restrict__ srcW,
                            const float* __restrict__ selfW,
                            const float* __restrict__ srcB,
                            const float* __restrict__ selfB) {
    int i = blockIdx.x * 256 + threadIdx.x;
    if (i < 512 * 128) {
        int n = i >> 7, k = i & 127;
        float v;
        if (n < 128)      v = e1W[k * 128 + n];
        else if (n < 256) v = e1W[(128 + k) * 128 + (n - 128)];
        else if (n < 384) v = srcW[k * 128 + (n - 256)];
        else              v = selfW[k * 128 + (n - 384)];
        g_Wn[i] = __float2bfloat16(v);
    }
    if (i < 256 * 128) {
        int n = i >> 7, k = i & 127;
        g_W2t[i] = __float2bfloat16(e2W[k * 256 + n]);
    }
    if (i < 512) {
        g_bn[i] = (i < 256) ? 0.0f : ((i < 384) ? srcB[i - 256] : selfB[i - 384]);
    }
}

__global__ void zero_kernel() {
    long i = (long)blockIdx.x * 256 + threadIdx.x;
    const long agg4 = (long)Nn * Hh / 4;
    if (i < agg4) ((float4*)g_agg)[i] = make_float4(0.f, 0.f, 0.f, 0.f);
    else if (i < agg4 + Nn / 4) ((float4*)g_indeg)[i - agg4] = make_float4(0.f, 0.f, 0.f, 0.f);
}

// ---------------------------------------------------------------------------
// K1: node projections via bf16 HMMA, P1/P2/S stored bf16, self fp32.
// ---------------------------------------------------------------------------
#define NP_SM_A 0
#define NP_SM_B 32768
#define NP_SM_BI 98304
#define NP_SMEM 99328

__global__ void __launch_bounds__(256, 2)
node_pre_mma(const float* __restrict__ h) {
    extern __shared__ char smem[];
    const uint32_t sbm = smem_u32(smem);
    const int tid = threadIdx.x;
    const int lane = tid & 31;
    const int wid = tid >> 5;
    const int tile = blockIdx.x;
    const int half = blockIdx.y;
    float* bi_s = (float*)(smem + NP_SM_BI);

#pragma unroll
    for (int it = 0; it < 8; it++) {
        int idx = tid + it * 256;
        int row = idx >> 4, c = idx & 15;
        int node = tile * 128 + row;
        uint4 w = make_uint4(0u, 0u, 0u, 0u);
        if (node < Nn) {
            const float4* p = (const float4*)(h + (long)node * 128 + c * 8);
            float4 v0 = p[0], v1 = p[1];
            w.x = pack_bf16(v0.x, v0.y); w.y = pack_bf16(v0.z, v0.w);
            w.z = pack_bf16(v1.x, v1.y); w.w = pack_bf16(v1.z, v1.w);
        }
        *(uint4*)(smem + NP_SM_A + row * 256 + ((c ^ (row & 7)) << 4)) = w;
    }
#pragma unroll
    for (int it = 0; it < 16; it++) {
        int idx = tid + it * 256;
        int n = idx >> 4, c = idx & 15;
        uint4 v = *(const uint4*)(g_Wn + (long)(half * 256 + n) * 128 + c * 8);
        *(uint4*)(smem + NP_SM_B + n * 256 + ((c ^ (n & 7)) << 4)) = v;
    }
    if (tid < 256) bi_s[tid] = g_bn[half * 256 + tid];
    __syncthreads();

    uint32_t Af[8][4];
    {
        int ts = lane >> 3;
        int row = wid * 16 + ((ts & 1) << 3) + (lane & 7);
        int rx = row & 7;
        uint32_t rb = sbm + NP_SM_A + row * 256;
#pragma unroll
        for (int kb = 0; kb < 8; kb++) {
            int c = kb * 2 + (ts >> 1);
            ldsm_x4(Af[kb], rb + ((c ^ rx) << 4));
        }
    }

    const int tsel = lane >> 3;
    const int jj_l = tsel >> 1;
    const int kh_l = tsel & 1;
    const int l7 = lane & 7;
    const int r0 = lane >> 2;
    const int cb2 = (lane & 3) * 2;

#pragma unroll 1
    for (int p = 0; p < 16; p++) {
        float C[2][4] = {{0.f,0.f,0.f,0.f},{0.f,0.f,0.f,0.f}};
        const int ng = p * 16 + jj_l * 8 + l7;
#pragma unroll
        for (int kb = 0; kb < 8; kb++) {
            uint32_t Bf[4];
            int c = kb * 2 + kh_l;
            ldsm_x4(Bf, sbm + NP_SM_B + ng * 256 + ((c ^ (ng & 7)) << 4));
            mma_bf16(C[0], Af[kb], Bf);
            mma_bf16(C[1], Af[kb], Bf + 2);
        }
#pragma unroll
        for (int jj = 0; jj < 2; jj++) {
            int nl = (2 * p + jj) * 8 + cb2;
            int n = half * 256 + nl;
            float2 bias = *(const float2*)(bi_s + nl);
            int nm = n & 127;
#pragma unroll
            for (int rh = 0; rh < 2; rh++) {
                int row = wid * 16 + r0 + rh * 8;
                int node = tile * 128 + row;
                if (node < Nn) {
                    float v0 = C[jj][rh * 2] + bias.x;
                    float v1 = C[jj][rh * 2 + 1] + bias.y;
                    if (n < 384) {
                        __nv_bfloat16* dstb = (n < 128) ? g_P1b : (n < 256) ? g_P2b : g_Sb;
                        *(__nv_bfloat162*)(dstb + (long)node * 128 + nm) =
                            __float22bfloat162_rn(make_float2(v0, v1));
                    } else {
                        *(float2*)(g_self + (long)node * 128 + nm) = make_float2(v0, v1);
                    }
                }
            }
        }
    }
}

// ---------------------------------------------------------------------------
// K2: persistent edge kernel, EB=128, M=16/warp, bf16 gathers.
// ---------------------------------------------------------------------------
#define SM_B2   0
#define SM_W1T  65536
#define SM_EST  69632
#define SM_B1   73728
#define SM_B2B  74240
#define SM_SRC  75264
#define SM_DST  75776
#define SMEM_EDGE 76288

__global__ void __launch_bounds__(256, 2)
edge_kernel(const float* __restrict__ eattr,
            const int* __restrict__ eidx,
            const float* __restrict__ e1W,
            const float* __restrict__ e1b,
            const float* __restrict__ e2b) {
    extern __shared__ char smem[];
    const uint32_t sbm = smem_u32(smem);
    const int tid = threadIdx.x;
    const int lane = tid & 31;
    const int wid = tid >> 5;
    float* b1_s = (float*)(smem + SM_B1);
    float* b2_s = (float*)(smem + SM_B2B);
    int* src_s  = (int*)(smem + SM_SRC);
    int* dst_s  = (int*)(smem + SM_DST);

#pragma unroll
    for (int it = 0; it < 16; it++) {
        int idx = tid + it * 256;
        int n = idx >> 4, c = idx & 15;
        uint4 v = *(const uint4*)(g_W2t + n * 128 + c * 8);
        *(uint4*)(smem + SM_B2 + n * 256 + ((c ^ (n & 7)) << 4)) = v;
    }
    for (int i = tid; i < 128 * 16; i += 256) {
        int n = i >> 4, k = i & 15;
        ((__nv_bfloat16*)(smem + SM_W1T))[n * 16 + k] =
            __float2bfloat16(e1W[(256 + k) * 128 + n]);
    }
    if (tid < 128) b1_s[tid] = e1b[tid];
    b2_s[tid & 255] = e2b[tid & 255];

    const int m0 = wid * 16;
    const int r0 = lane >> 2;
    const int rowA = m0 + r0, rowB = rowA + 8;
    const int cbase = (lane & 3) * 2;
    const int tl8 = lane & 15;
    const int tsel = lane >> 3;
    const int jj_l = tsel >> 1;
    const int kh_l = tsel & 1;
    const int l7 = lane & 7;

    for (int tile = blockIdx.x; tile < NT; tile += EGRID) {
        const long eb = (long)tile * EB;
        const int remaining = (int)(Ee - eb);
        __syncthreads();

        if (tid < 128) {
            long e = eb + tid;
            int s = 0, d = 0;
            if (tid < remaining) {
                s = eidx[2 * e];
                d = eidx[2 * e + 1];
                atomicAdd(&g_indeg[d], 1.0f);
            }
            src_s[tid] = s;
            dst_s[tid] = d;
        }
        {
            int erow = tid >> 1;
            long e = eb + erow;
            long ec = (erow < remaining) ? e : eb;
            const float4* p = (const float4*)(eattr + ec * 16 + (tid & 1) * 8);
            float4 v0 = p[0], v1 = p[1];
            uint4 w;
            w.x = pack_bf16(v0.x, v0.y); w.y = pack_bf16(v0.z, v0.w);
            w.z = pack_bf16(v1.x, v1.y); w.w = pack_bf16(v1.z, v1.w);
            *(uint4*)(smem + SM_EST + erow * 32 + (tid & 1) * 16) = w;
        }
        __syncthreads();

        const int sa = src_s[rowA], da = dst_s[rowA];
        const int sb2 = src_s[rowB], db = dst_s[rowB];
        const __nv_bfloat16* p1a = g_P1b + (long)sa * Hh;
        const __nv_bfloat16* p2a = g_P2b + (long)da * Hh;
        const __nv_bfloat16* p1b = g_P1b + (long)sb2 * Hh;
        const __nv_bfloat16* p2b = g_P2b + (long)db * Hh;

        // ---- C1 init = P1[s] + P2[d] + b1 (bf16 gathers) ----
        float C1[16][4];
#pragma unroll
        for (int j = 0; j < 16; j++) {
            int c = j * 8 + cbase;
            float2 x1 = bf2f(p1a + c);
            float2 x2 = bf2f(p2a + c);
            float2 y1 = bf2f(p1b + c);
            float2 y2 = bf2f(p2b + c);
            float2 bb = *(const float2*)(b1_s + c);
            C1[j][0] = x1.x + x2.x + bb.x;
            C1[j][1] = x1.y + x2.y + bb.y;
            C1[j][2] = y1.x + y2.x + bb.x;
            C1[j][3] = y1.y + y2.y + bb.y;
        }

        // ---- MMA1: C1 += eattr(16) @ W1e(16x128) ----
        uint32_t A1[4];
        {
            int row = m0 + ((tsel & 1) << 3) + l7;
            ldsm_x4(A1, sbm + SM_EST + row * 32 + ((tsel >> 1) << 4));
        }
#pragma unroll
        for (int j = 0; j < 16; j++) {
            uint32_t Bf[2];
            int n = j * 8 + (tl8 & 7);
            ldsm_x2(Bf, sbm + SM_W1T + n * 32 + ((tl8 >> 3) << 4));
            mma_bf16(C1[j], A1, Bf);
        }

        // ---- GELU + repack ----
        uint32_t A2[8][4];
#pragma unroll
        for (int kb = 0; kb < 8; kb++) {
            A2[kb][0] = pack_bf16(gelu_exact(C1[2 * kb][0]),     gelu_exact(C1[2 * kb][1]));
            A2[kb][1] = pack_bf16(gelu_exact(C1[2 * kb][2]),     gelu_exact(C1[2 * kb][3]));
            A2[kb][2] = pack_bf16(gelu_exact(C1[2 * kb + 1][0]), gelu_exact(C1[2 * kb + 1][1]));
            A2[kb][3] = pack_bf16(gelu_exact(C1[2 * kb + 1][2]), gelu_exact(C1[2 * kb + 1][3]));
        }

        // ---- MMA2 + fused epilogue ----
        const bool va = (rowA < remaining), vb = (rowB < remaining);
        const __nv_bfloat16* Spa = g_Sb + (long)sa * Hh;
        const __nv_bfloat16* Spb = g_Sb + (long)sb2 * Hh;
        float* apa = g_agg + (long)da * Hh;
        float* apb = g_agg + (long)db * Hh;

#pragma unroll 1
        for (int g = 0; g < 8; g++) {
            float Cg[2][4] = {}, Cs[2][4] = {};
            const int ngl = (2 * g + jj_l) * 8 + l7;
            const int nsl = ngl + 128;
#pragma unroll
            for (int kb = 0; kb < 8; kb++) {
                uint32_t Bg[4], Bs[4];
                int c = kb * 2 + kh_l;
                ldsm_x4(Bg, sbm + SM_B2 + ngl * 256 + ((c ^ (ngl & 7)) << 4));
                ldsm_x4(Bs, sbm + SM_B2 + nsl * 256 + ((c ^ (nsl & 7)) << 4));
                mma_bf16(Cg[0], A2[kb], Bg);
                mma_bf16(Cg[1], A2[kb], Bg + 2);
                mma_bf16(Cs[0], A2[kb], Bs);
                mma_bf16(Cs[1], A2[kb], Bs + 2);
            }
#pragma unroll
            for (int jj = 0; jj < 2; jj++) {
                int c0 = (2 * g + jj) * 8 + cbase;
                float2 bg = *(const float2*)(b2_s + c0);
                float2 bsv = *(const float2*)(b2_s + 128 + c0);
                if (va) {
                    float2 sv = bf2f(Spa + c0);
                    float g0 = Cg[jj][0] + bg.x, g1 = Cg[jj][1] + bg.y;
                    float s0 = Cs[jj][0] + bsv.x, s1 = Cs[jj][1] + bsv.y;
                    float v0 = sv.x * __fdividef(1.0f, 1.0f + __expf(-g0)) + s0;
                    float v1 = sv.y * __fdividef(1.0f, 1.0f + __expf(-g1)) + s1;
                    asm volatile("red.global.add.v2.f32 [%0], {%1,%2};"
                                 :: "l"(apa + c0), "f"(v0), "f"(v1) : "memory");
                }
                if (vb) {
                    float2 sv = bf2f(Spb + c0);
                    float g0 = Cg[jj][2] + bg.x, g1 = Cg[jj][3] + bg.y;
                    float s0 = Cs[jj][2] + bsv.x, s1 = Cs[jj][3] + bsv.y;
                    float v0 = sv.x * __fdividef(1.0f, 1.0f + __expf(-g0)) + s0;
                    float v1 = sv.y * __fdividef(1.0f, 1.0f + __expf(-g1)) + s1;
                    asm volatile("red.global.add.v2.f32 [%0], {%1,%2};"
                                 :: "l"(apb + c0), "f"(v0), "f"(v1) : "memory");
                }
            }
        }
    }
}

// ---------------------------------------------------------------------------
// K3: node update + residual GELU + LayerNorm (16 nodes / block, 256 thr)
// ---------------------------------------------------------------------------
__global__ void __launch_bounds__(256)
node_update_kernel(const float* __restrict__ h,
                   const float* __restrict__ aggW,
                   const float* __restrict__ aggB,
                   const float* __restrict__ lng,
                   const float* __restrict__ lnb,
                   float* __restrict__ out) {
    __shared__ float sA[16][Hh];
    __shared__ float sX[16][Hh];

    const int tid = threadIdx.x;
    const int col = tid & 127;
    const int grp = tid >> 7;            // 0..1, owns nodes grp*8..grp*8+7
    const int nb = blockIdx.x * 16;      // Nn % 16 == 0

#pragma unroll
    for (int i = 0; i < 8; i++) {
        int ni = grp * 8 + i;
        int n = nb + ni;
        float rd = 1.0f / fmaxf(g_indeg[n], 1.0f);
        sA[ni][col] = g_agg[(long)n * Hh + col] * rd;
    }
    __syncthreads();

    float acc[8] = {};
#pragma unroll 4
    for (int k = 0; k < Hh; k++) {
        float w = __ldg(aggW + k * Hh + col);
#pragma unroll
        for (int i = 0; i < 8; i++) acc[i] += sA[grp * 8 + i][k] * w;
    }
    float ab = __ldg(aggB + col);
#pragma unroll
    for (int i = 0; i < 8; i++) {
        int ni = grp * 8 + i;
        int n = nb + ni;
        float u = g_self[(long)n * Hh + col] + acc[i] + ab;
        sX[ni][col] = h[(long)n * Hh + col] + gelu_exact(u);
    }
    __syncthreads();

    const int wid = tid >> 5, lane = tid & 31;
#pragma unroll
    for (int pass = 0; pass < 2; pass++) {
        int ni = wid + pass * 8;
        int n = nb + ni;
        float v[4], sm = 0.f, s2 = 0.f;
#pragma unroll
        for (int r = 0; r < 4; r++) {
            v[r] = sX[ni][lane + 32 * r];
            sm += v[r];
            s2 += v[r] * v[r];
        }
#pragma unroll
        for (int o = 16; o > 0; o >>= 1) {
            sm += __shfl_xor_sync(0xffffffff, sm, o);
            s2 += __shfl_xor_sync(0xffffffff, s2, o);
        }
        float mu = sm * (1.0f / Hh);
        float var = s2 * (1.0f / Hh) - mu * mu;
        float rstd = rsqrtf(var + LN_EPS);
#pragma unroll
        for (int r = 0; r < 4; r++) {
            int j = lane + 32 * r;
            out[(long)n * Hh + j] = (v[r] - mu) * rstd * __ldg(lng + j) + __ldg(lnb + j);
        }
    }
}

// ---------------------------------------------------------------------------
extern "C" void kernel_launch(void* const* d_in, const int* in_sizes, int n_in,
                              void* d_out, int out_size) {
    const float* h     = (const float*)d_in[0];
    const float* eattr = (const float*)d_in[1];
    const int*   eidx  = (const int*)d_in[2];
    const float* srcW  = (const float*)d_in[3];
    const float* srcB  = (const float*)d_in[4];
    const float* e1W   = (const float*)d_in[5];
    const float* e1b   = (const float*)d_in[6];
    const float* e2W   = (const float*)d_in[7];
    const float* e2b   = (const float*)d_in[8];
    const float* selfW = (const float*)d_in[9];
    const float* selfB = (const float*)d_in[10];
    const float* aggW  = (const float*)d_in[11];
    const float* aggB  = (const float*)d_in[12];
    const float* lng   = (const float*)d_in[13];
    const float* lnb   = (const float*)d_in[14];
    float* out = (float*)d_out;

    cudaFuncSetAttribute(edge_kernel, cudaFuncAttributeMaxDynamicSharedMemorySize, SMEM_EDGE);
    cudaFuncSetAttribute(node_pre_mma, cudaFuncAttributeMaxDynamicSharedMemorySize, NP_SMEM);

    long zero_elems = (long)Nn * Hh / 4 + Nn / 4;
    zero_kernel<<<(int)((zero_elems + 255) / 256), 256>>>();
    prep_kernel<<<256, 256>>>(e2W, e1W, srcW, selfW, srcB, selfB);
    node_pre_mma<<<dim3((Nn + 127) / 128, 2), 256, NP_SMEM>>>(h);
    edge_kernel<<<EGRID, 256, SMEM_EDGE>>>(eattr, eidx, e1W, e1b, e2b);
    node_update_kernel<<<Nn / 16, 256>>>(h, aggW, aggB, lng, lnb, out);
}

// round 9
// speedup vs baseline: 5.1376x; 1.0353x over previous
#include <cuda_runtime.h>
#include <cuda_bf16.h>
#include <math.h>
#include <cstdint>

#define Hh 128
#define Nn 50000
#define Ee 500000
#define LN_EPS 1e-5f
#define EB 128
#define NT ((Ee + EB - 1) / EB)     // 3907 tiles
#define EGRID 296

// ---------------- scratch ----------------
__device__ __align__(16) __nv_bfloat16 g_P1b[Nn * Hh];
__device__ __align__(16) __nv_bfloat16 g_P2b[Nn * Hh];
__device__ __align__(16) __nv_bfloat16 g_Sb[Nn * Hh];
__device__ float g_self[Nn * Hh];
__device__ float g_agg[Nn * Hh];
__device__ float g_indeg[Nn];
__device__ __align__(16) __nv_bfloat16 g_W2t[256 * 128];
__device__ __align__(16) __nv_bfloat16 g_Wn[512 * 128];
__device__ float g_bn[512];

__device__ __forceinline__ float gelu_exact(float x) {
    return 0.5f * x * (1.0f + erff(x * 0.70710678118654752440f));
}
__device__ __forceinline__ uint32_t smem_u32(const void* p) {
    uint32_t a;
    asm("{ .reg .u64 t; cvta.to.shared.u64 t, %1; cvt.u32.u64 %0, t; }" : "=r"(a) : "l"(p));
    return a;
}
__device__ __forceinline__ void ldsm_x4(uint32_t* r, uint32_t addr) {
    asm volatile("ldmatrix.sync.aligned.m8n8.x4.shared.b16 {%0,%1,%2,%3}, [%4];"
                 : "=r"(r[0]), "=r"(r[1]), "=r"(r[2]), "=r"(r[3]) : "r"(addr));
}
__device__ __forceinline__ void ldsm_x2(uint32_t* r, uint32_t addr) {
    asm volatile("ldmatrix.sync.aligned.m8n8.x2.shared.b16 {%0,%1}, [%2];"
                 : "=r"(r[0]), "=r"(r[1]) : "r"(addr));
}
__device__ __forceinline__ void mma_bf16(float* c, const uint32_t* a, const uint32_t* b) {
    asm volatile(
        "mma.sync.aligned.m16n8k16.row.col.f32.bf16.bf16.f32 "
        "{%0,%1,%2,%3},{%4,%5,%6,%7},{%8,%9},{%0,%1,%2,%3};"
        : "+f"(c[0]), "+f"(c[1]), "+f"(c[2]), "+f"(c[3])
        : "r"(a[0]), "r"(a[1]), "r"(a[2]), "r"(a[3]), "r"(b[0]), "r"(b[1]));
}
__device__ __forceinline__ uint32_t pack_bf16(float a, float b) {
    __nv_bfloat162 t = __float22bfloat162_rn(make_float2(a, b));
    return *reinterpret_cast<uint32_t*>(&t);
}
__device__ __forceinline__ float2 bf2f(const __nv_bfloat16* p) {
    return __bfloat1622float2(*(const __nv_bfloat162*)p);
}

// ---------------------------------------------------------------------------
__global__ void prep_kernel(const float* __restrict__ e2W,
                            const float* __restrict__ e1W,
                            const float* __restrict__ srcW,
                            const float* __restrict__ selfW,
                            const float* __restrict__ srcB,
                            const float* __restrict__ selfB) {
    int i = blockIdx.x * 256 + threadIdx.x;
    if (i < 512 * 128) {
        int n = i >> 7, k = i & 127;
        float v;
        if (n < 128)      v = e1W[k * 128 + n];
        else if (n < 256) v = e1W[(128 + k) * 128 + (n - 128)];
        else if (n < 384) v = srcW[k * 128 + (n - 256)];
        else              v = selfW[k * 128 + (n - 384)];
        g_Wn[i] = __float2bfloat16(v);
    }
    if (i < 256 * 128) {
        int n = i >> 7, k = i & 127;
        g_W2t[i] = __float2bfloat16(e2W[k * 256 + n]);
    }
    if (i < 512) {
        g_bn[i] = (i < 256) ? 0.0f : ((i < 384) ? srcB[i - 256] : selfB[i - 384]);
    }
}

__global__ void zero_kernel() {
    long i = (long)blockIdx.x * 256 + threadIdx.x;
    const long agg4 = (long)Nn * Hh / 4;
    if (i < agg4) ((float4*)g_agg)[i] = make_float4(0.f, 0.f, 0.f, 0.f);
    else if (i < agg4 + Nn / 4) ((float4*)g_indeg)[i - agg4] = make_float4(0.f, 0.f, 0.f, 0.f);
}

// ---------------------------------------------------------------------------
// K1: node projections via bf16 HMMA (unchanged from R8)
// ---------------------------------------------------------------------------
#define NP_SM_A 0
#define NP_SM_B 32768
#define NP_SM_BI 98304
#define NP_SMEM 99328

__global__ void __launch_bounds__(256, 2)
node_pre_mma(const float* __restrict__ h) {
    extern __shared__ char smem[];
    const uint32_t sbm = smem_u32(smem);
    const int tid = threadIdx.x;
    const int lane = tid & 31;
    const int wid = tid >> 5;
    const int tile = blockIdx.x;
    const int half = blockIdx.y;
    float* bi_s = (float*)(smem + NP_SM_BI);

#pragma unroll
    for (int it = 0; it < 8; it++) {
        int idx = tid + it * 256;
        int row = idx >> 4, c = idx & 15;
        int node = tile * 128 + row;
        uint4 w = make_uint4(0u, 0u, 0u, 0u);
        if (node < Nn) {
            const float4* p = (const float4*)(h + (long)node * 128 + c * 8);
            float4 v0 = p[0], v1 = p[1];
            w.x = pack_bf16(v0.x, v0.y); w.y = pack_bf16(v0.z, v0.w);
            w.z = pack_bf16(v1.x, v1.y); w.w = pack_bf16(v1.z, v1.w);
        }
        *(uint4*)(smem + NP_SM_A + row * 256 + ((c ^ (row & 7)) << 4)) = w;
    }
#pragma unroll
    for (int it = 0; it < 16; it++) {
        int idx = tid + it * 256;
        int n = idx >> 4, c = idx & 15;
        uint4 v = *(const uint4*)(g_Wn + (long)(half * 256 + n) * 128 + c * 8);
        *(uint4*)(smem + NP_SM_B + n * 256 + ((c ^ (n & 7)) << 4)) = v;
    }
    if (tid < 256) bi_s[tid] = g_bn[half * 256 + tid];
    __syncthreads();

    uint32_t Af[8][4];
    {
        int ts = lane >> 3;
        int row = wid * 16 + ((ts & 1) << 3) + (lane & 7);
        int rx = row & 7;
        uint32_t rb = sbm + NP_SM_A + row * 256;
#pragma unroll
        for (int kb = 0; kb < 8; kb++) {
            int c = kb * 2 + (ts >> 1);
            ldsm_x4(Af[kb], rb + ((c ^ rx) << 4));
        }
    }

    const int tsel = lane >> 3;
    const int jj_l = tsel >> 1;
    const int kh_l = tsel & 1;
    const int l7 = lane & 7;
    const int r0 = lane >> 2;
    const int cb2 = (lane & 3) * 2;

#pragma unroll 1
    for (int p = 0; p < 16; p++) {
        float C[2][4] = {{0.f,0.f,0.f,0.f},{0.f,0.f,0.f,0.f}};
        const int ng = p * 16 + jj_l * 8 + l7;
#pragma unroll
        for (int kb = 0; kb < 8; kb++) {
            uint32_t Bf[4];
            int c = kb * 2 + kh_l;
            ldsm_x4(Bf, sbm + NP_SM_B + ng * 256 + ((c ^ (ng & 7)) << 4));
            mma_bf16(C[0], Af[kb], Bf);
            mma_bf16(C[1], Af[kb], Bf + 2);
        }
#pragma unroll
        for (int jj = 0; jj < 2; jj++) {
            int nl = (2 * p + jj) * 8 + cb2;
            int n = half * 256 + nl;
            float2 bias = *(const float2*)(bi_s + nl);
            int nm = n & 127;
#pragma unroll
            for (int rh = 0; rh < 2; rh++) {
                int row = wid * 16 + r0 + rh * 8;
                int node = tile * 128 + row;
                if (node < Nn) {
                    float v0 = C[jj][rh * 2] + bias.x;
                    float v1 = C[jj][rh * 2 + 1] + bias.y;
                    if (n < 384) {
                        __nv_bfloat16* dstb = (n < 128) ? g_P1b : (n < 256) ? g_P2b : g_Sb;
                        *(__nv_bfloat162*)(dstb + (long)node * 128 + nm) =
                            __float22bfloat162_rn(make_float2(v0, v1));
                    } else {
                        *(float2*)(g_self + (long)node * 128 + nm) = make_float2(v0, v1);
                    }
                }
            }
        }
    }
}

// ---------------------------------------------------------------------------
// K2: persistent edge kernel — direct idx loads, EST double-buffer,
//     single sync/tile, MMA1 before gather-adds.
// smem: B2 65536 @0 ; W1T 4096 @65536 ; EST 2x4096 @69632 ;
//       b1 512 @77824 ; b2 1024 @78336  -> 79360
// ---------------------------------------------------------------------------
#define SM_B2   0
#define SM_W1T  65536
#define SM_EST  69632
#define SM_B1   77824
#define SM_B2B  78336
#define SMEM_EDGE 79360

__global__ void __launch_bounds__(256, 2)
edge_kernel(const float* __restrict__ eattr,
            const int* __restrict__ eidx,
            const float* __restrict__ e1W,
            const float* __restrict__ e1b,
            const float* __restrict__ e2b) {
    extern __shared__ char smem[];
    const uint32_t sbm = smem_u32(smem);
    const int tid = threadIdx.x;
    const int lane = tid & 31;
    const int wid = tid >> 5;
    float* b1_s = (float*)(smem + SM_B1);
    float* b2_s = (float*)(smem + SM_B2B);

    // ---- one-time staging ----
#pragma unroll
    for (int it = 0; it < 16; it++) {
        int idx = tid + it * 256;
        int n = idx >> 4, c = idx & 15;
        uint4 v = *(const uint4*)(g_W2t + n * 128 + c * 8);
        *(uint4*)(smem + SM_B2 + n * 256 + ((c ^ (n & 7)) << 4)) = v;
    }
    for (int i = tid; i < 128 * 16; i += 256) {
        int n = i >> 4, k = i & 15;
        ((__nv_bfloat16*)(smem + SM_W1T))[n * 16 + k] =
            __float2bfloat16(e1W[(256 + k) * 128 + n]);
    }
    if (tid < 128) b1_s[tid] = e1b[tid];
    b2_s[tid & 255] = e2b[tid & 255];

    const int m0 = wid * 16;
    const int r0 = lane >> 2;
    const int rowA = m0 + r0, rowB = rowA + 8;
    const int cbase = (lane & 3) * 2;
    const int tl8 = lane & 15;
    const int tsel = lane >> 3;
    const int jj_l = tsel >> 1;
    const int kh_l = tsel & 1;
    const int l7 = lane & 7;
    const int erow = tid >> 1;
    const int ehalf = (tid & 1);

    // ---- prologue: stage EST for first tile into buf 0 ----
    {
        long e = (long)blockIdx.x * EB + erow;
        long ec = (e < Ee) ? e : 0;
        const float4* p = (const float4*)(eattr + ec * 16 + ehalf * 8);
        float4 v0 = p[0], v1 = p[1];
        uint4 w;
        w.x = pack_bf16(v0.x, v0.y); w.y = pack_bf16(v0.z, v0.w);
        w.z = pack_bf16(v1.x, v1.y); w.w = pack_bf16(v1.z, v1.w);
        *(uint4*)(smem + SM_EST + erow * 32 + ehalf * 16) = w;
    }

    int lt = 0;
    for (int tile = blockIdx.x; tile < NT; tile += EGRID, lt++) {
        const long eb = (long)tile * EB;
        const int remaining = (int)(Ee - eb);

        // ---- per-row indices, direct from gmem (pre-sync) ----
        int sa = 0, da = 0, sb2 = 0, db = 0;
        const bool va = (rowA < remaining), vb = (rowB < remaining);
        if (va) { int2 ii = *(const int2*)(eidx + 2 * (eb + rowA)); sa = ii.x; da = ii.y; }
        if (vb) { int2 ii = *(const int2*)(eidx + 2 * (eb + rowB)); sb2 = ii.x; db = ii.y; }
        if ((lane & 3) == 0) {
            if (va) atomicAdd(&g_indeg[da], 1.0f);
            if (vb) atomicAdd(&g_indeg[db], 1.0f);
        }

        __syncthreads();   // EST(t) visible; prior-tile EST reads done
        const uint32_t estb = sbm + SM_EST + (lt & 1) * 4096;

        // ---- C1 = b1 (broadcast), then MMA1 (smem-only) ----
        float C1[16][4];
#pragma unroll
        for (int j = 0; j < 16; j++) {
            float2 bb = *(const float2*)(b1_s + j * 8 + cbase);
            C1[j][0] = bb.x; C1[j][1] = bb.y;
            C1[j][2] = bb.x; C1[j][3] = bb.y;
        }
        uint32_t A1[4];
        {
            int row = m0 + ((tsel & 1) << 3) + l7;
            ldsm_x4(A1, estb + row * 32 + ((tsel >> 1) << 4));
        }
#pragma unroll
        for (int j = 0; j < 16; j++) {
            uint32_t Bf[2];
            int n = j * 8 + (tl8 & 7);
            ldsm_x2(Bf, sbm + SM_W1T + n * 32 + ((tl8 >> 3) << 4));
            mma_bf16(C1[j], A1, Bf);
        }

        // ---- stage EST for next tile into the other buffer ----
        if (tile + EGRID < NT) {
            long e = (long)(tile + EGRID) * EB + erow;
            long ec = (e < Ee) ? e : 0;
            const float4* p = (const float4*)(eattr + ec * 16 + ehalf * 8);
            float4 v0 = p[0], v1 = p[1];
            uint4 w;
            w.x = pack_bf16(v0.x, v0.y); w.y = pack_bf16(v0.z, v0.w);
            w.z = pack_bf16(v1.x, v1.y); w.w = pack_bf16(v1.z, v1.w);
            *(uint4*)(smem + SM_EST + ((lt + 1) & 1) * 4096 + erow * 32 + ehalf * 16) = w;
        }

        // ---- gather-adds: C1 += P1[s] + P2[d] ----
        const __nv_bfloat16* p1a = g_P1b + (long)sa * Hh;
        const __nv_bfloat16* p2a = g_P2b + (long)da * Hh;
        const __nv_bfloat16* p1b = g_P1b + (long)sb2 * Hh;
        const __nv_bfloat16* p2b = g_P2b + (long)db * Hh;
#pragma unroll
        for (int j = 0; j < 16; j++) {
            int c = j * 8 + cbase;
            float2 x1 = bf2f(p1a + c);
            float2 x2 = bf2f(p2a + c);
            float2 y1 = bf2f(p1b + c);
            float2 y2 = bf2f(p2b + c);
            C1[j][0] += x1.x + x2.x; C1[j][1] += x1.y + x2.y;
            C1[j][2] += y1.x + y2.x; C1[j][3] += y1.y + y2.y;
        }

        // ---- GELU + repack ----
        uint32_t A2[8][4];
#pragma unroll
        for (int kb = 0; kb < 8; kb++) {
            A2[kb][0] = pack_bf16(gelu_exact(C1[2 * kb][0]),     gelu_exact(C1[2 * kb][1]));
            A2[kb][1] = pack_bf16(gelu_exact(C1[2 * kb][2]),     gelu_exact(C1[2 * kb][3]));
            A2[kb][2] = pack_bf16(gelu_exact(C1[2 * kb + 1][0]), gelu_exact(C1[2 * kb + 1][1]));
            A2[kb][3] = pack_bf16(gelu_exact(C1[2 * kb + 1][2]), gelu_exact(C1[2 * kb + 1][3]));
        }

        // ---- MMA2 + fused epilogue ----
        const __nv_bfloat16* Spa = g_Sb + (long)sa * Hh;
        const __nv_bfloat16* Spb = g_Sb + (long)sb2 * Hh;
        float* apa = g_agg + (long)da * Hh;
        float* apb = g_agg + (long)db * Hh;

#pragma unroll 1
        for (int g = 0; g < 8; g++) {
            float Cg[2][4] = {}, Cs[2][4] = {};
            const int ngl = (2 * g + jj_l) * 8 + l7;
            const int nsl = ngl + 128;
#pragma unroll
            for (int kb = 0; kb < 8; kb++) {
                uint32_t Bg[4], Bs[4];
                int c = kb * 2 + kh_l;
                ldsm_x4(Bg, sbm + SM_B2 + ngl * 256 + ((c ^ (ngl & 7)) << 4));
                ldsm_x4(Bs, sbm + SM_B2 + nsl * 256 + ((c ^ (nsl & 7)) << 4));
                mma_bf16(Cg[0], A2[kb], Bg);
                mma_bf16(Cg[1], A2[kb], Bg + 2);
                mma_bf16(Cs[0], A2[kb], Bs);
                mma_bf16(Cs[1], A2[kb], Bs + 2);
            }
#pragma unroll
            for (int jj = 0; jj < 2; jj++) {
                int c0 = (2 * g + jj) * 8 + cbase;
                float2 bg = *(const float2*)(b2_s + c0);
                float2 bsv = *(const float2*)(b2_s + 128 + c0);
                if (va) {
                    float2 sv = bf2f(Spa + c0);
                    float g0 = Cg[jj][0] + bg.x, g1 = Cg[jj][1] + bg.y;
                    float s0 = Cs[jj][0] + bsv.x, s1 = Cs[jj][1] + bsv.y;
                    float v0 = sv.x * __fdividef(1.0f, 1.0f + __expf(-g0)) + s0;
                    float v1 = sv.y * __fdividef(1.0f, 1.0f + __expf(-g1)) + s1;
                    asm volatile("red.global.add.v2.f32 [%0], {%1,%2};"
                                 :: "l"(apa + c0), "f"(v0), "f"(v1) : "memory");
                }
                if (vb) {
                    float2 sv = bf2f(Spb + c0);
                    float g0 = Cg[jj][2] + bg.x, g1 = Cg[jj][3] + bg.y;
                    float s0 = Cs[jj][2] + bsv.x, s1 = Cs[jj][3] + bsv.y;
                    float v0 = sv.x * __fdividef(1.0f, 1.0f + __expf(-g0)) + s0;
                    float v1 = sv.y * __fdividef(1.0f, 1.0f + __expf(-g1)) + s1;
                    asm volatile("red.global.add.v2.f32 [%0], {%1,%2};"
                                 :: "l"(apb + c0), "f"(v0), "f"(v1) : "memory");
                }
            }
        }
    }
}

// ---------------------------------------------------------------------------
// K3: node update + residual GELU + LayerNorm (16 nodes / block, 256 thr)
// ---------------------------------------------------------------------------
__global__ void __launch_bounds__(256)
node_update_kernel(const float* __restrict__ h,
                   const float* __restrict__ aggW,
                   const float* __restrict__ aggB,
                   const float* __restrict__ lng,
                   const float* __restrict__ lnb,
                   float* __restrict__ out) {
    __shared__ float sA[16][Hh];
    __shared__ float sX[16][Hh];

    const int tid = threadIdx.x;
    const int col = tid & 127;
    const int grp = tid >> 7;
    const int nb = blockIdx.x * 16;

#pragma unroll
    for (int i = 0; i < 8; i++) {
        int ni = grp * 8 + i;
        int n = nb + ni;
        float rd = 1.0f / fmaxf(g_indeg[n], 1.0f);
        sA[ni][col] = g_agg[(long)n * Hh + col] * rd;
    }
    __syncthreads();

    float acc[8] = {};
#pragma unroll 4
    for (int k = 0; k < Hh; k++) {
        float w = __ldg(aggW + k * Hh + col);
#pragma unroll
        for (int i = 0; i < 8; i++) acc[i] += sA[grp * 8 + i][k] * w;
    }
    float ab = __ldg(aggB + col);
#pragma unroll
    for (int i = 0; i < 8; i++) {
        int ni = grp * 8 + i;
        int n = nb + ni;
        float u = g_self[(long)n * Hh + col] + acc[i] + ab;
        sX[ni][col] = h[(long)n * Hh + col] + gelu_exact(u);
    }
    __syncthreads();

    const int wid = tid >> 5, lane = tid & 31;
#pragma unroll
    for (int pass = 0; pass < 2; pass++) {
        int ni = wid + pass * 8;
        int n = nb + ni;
        float v[4], sm = 0.f, s2 = 0.f;
#pragma unroll
        for (int r = 0; r < 4; r++) {
            v[r] = sX[ni][lane + 32 * r];
            sm += v[r];
            s2 += v[r] * v[r];
        }
#pragma unroll
        for (int o = 16; o > 0; o >>= 1) {
            sm += __shfl_xor_sync(0xffffffff, sm, o);
            s2 += __shfl_xor_sync(0xffffffff, s2, o);
        }
        float mu = sm * (1.0f / Hh);
        float var = s2 * (1.0f / Hh) - mu * mu;
        float rstd = rsqrtf(var + LN_EPS);
#pragma unroll
        for (int r = 0; r < 4; r++) {
            int j = lane + 32 * r;
            out[(long)n * Hh + j] = (v[r] - mu) * rstd * __ldg(lng + j) + __ldg(lnb + j);
        }
    }
}

// ---------------------------------------------------------------------------
extern "C" void kernel_launch(void* const* d_in, const int* in_sizes, int n_in,
                              void* d_out, int out_size) {
    const float* h     = (const float*)d_in[0];
    const float* eattr = (const float*)d_in[1];
    const int*   eidx  = (const int*)d_in[2];
    const float* srcW  = (const float*)d_in[3];
    const float* srcB  = (const float*)d_in[4];
    const float* e1W   = (const float*)d_in[5];
    const float* e1b   = (const float*)d_in[6];
    const float* e2W   = (const float*)d_in[7];
    const float* e2b   = (const float*)d_in[8];
    const float* selfW = (const float*)d_in[9];
    const float* selfB = (const float*)d_in[10];
    const float* aggW  = (const float*)d_in[11];
    const float* aggB  = (const float*)d_in[12];
    const float* lng   = (const float*)d_in[13];
    const float* lnb   = (const float*)d_in[14];
    float* out = (float*)d_out;

    cudaFuncSetAttribute(edge_kernel, cudaFuncAttributeMaxDynamicSharedMemorySize, SMEM_EDGE);
    cudaFuncSetAttribute(node_pre_mma, cudaFuncAttributeMaxDynamicSharedMemorySize, NP_SMEM);

    long zero_elems = (long)Nn * Hh / 4 + Nn / 4;
    zero_kernel<<<(int)((zero_elems + 255) / 256), 256>>>();
    prep_kernel<<<256, 256>>>(e2W, e1W, srcW, selfW, srcB, selfB);
    node_pre_mma<<<dim3((Nn + 127) / 128, 2), 256, NP_SMEM>>>(h);
    edge_kernel<<<EGRID, 256, SMEM_EDGE>>>(eattr, eidx, e1W, e1b, e2b);
    node_update_kernel<<<Nn / 16, 256>>>(h, aggW, aggB, lng, lnb, out);
}